// round 7
// baseline (speedup 1.0000x reference)
#include <cuda_runtime.h>
#include <cstdint>

// Problem constants
#define BB    4
#define SS    2048
#define DM    1024
#define NH    16
#define DH    64
#define TOK   (BB * SS)          // 8192 tokens

// ---------------- scratch (no cudaMalloc allowed) ----------------
__device__ float g_q[TOK * DM];     // [B,H,S,Dh]  tf32, Dh PAIR-PERMUTED
__device__ float g_k[TOK * DM];     // [B,H,S,Dh]  tf32, Dh PAIR-PERMUTED
__device__ float g_v[TOK * DM];     // [B,H,S,Dh]  tf32, natural order
__device__ float g_attn[TOK * DM];  // [B,S,D]     tf32-rounded by attn epilogue
__device__ float g_qin[TOK * DM];   // RNA-rounded inputs
__device__ float g_kin[TOK * DM];
__device__ float g_vin[TOK * DM];
__device__ float g_wq[DM * DM];     // RNA-rounded weights
__device__ float g_wk[DM * DM];
__device__ float g_wv[DM * DM];
__device__ float g_wo[DM * DM];

// ---------------- helpers ----------------
__device__ __forceinline__ uint32_t f2tf32(float x) {
    uint32_t u;
    asm("cvt.rna.tf32.f32 %0, %1;" : "=r"(u) : "f"(x));
    return u;
}
__device__ __forceinline__ float f2tf32f(float x) {
    return __uint_as_float(f2tf32(x));
}

__device__ __forceinline__ uint32_t smem_u32(const void* p) {
    uint32_t a;
    asm("{ .reg .u64 t; cvta.to.shared.u64 t, %1; cvt.u32.u64 %0, t; }" : "=r"(a) : "l"(p));
    return a;
}

__device__ __forceinline__ void cpasync16(uint32_t dst, const void* src) {
    asm volatile("cp.async.cg.shared.global [%0], [%1], 16;" :: "r"(dst), "l"(src));
}
#define CP_COMMIT()  asm volatile("cp.async.commit_group;" ::: "memory")
#define CP_WAIT(n)   asm volatile("cp.async.wait_group " #n ";" ::: "memory")

__device__ __forceinline__ void mma8(float* c, const uint32_t* a, const uint32_t* b) {
    asm volatile(
        "mma.sync.aligned.m16n8k8.row.col.f32.tf32.tf32.f32 "
        "{%0,%1,%2,%3},{%4,%5,%6,%7},{%8,%9},{%0,%1,%2,%3};\n"
        : "+f"(c[0]), "+f"(c[1]), "+f"(c[2]), "+f"(c[3])
        : "r"(a[0]), "r"(a[1]), "r"(a[2]), "r"(a[3]),
          "r"(b[0]), "r"(b[1]));
}

// pair-permutation within 8-group: (0..3) -> even slots, (4..7) -> odd slots
// so fragment cols (t, t+4) land at contiguous slots (2t, 2t+1)
__device__ __forceinline__ int perm8(int a) { return (a < 4) ? 2 * a : 2 * a - 7; }

// ---------------- fused RNA tf32 rounding pass (7 arrays, 1 launch) ----------------
#define N4I (TOK * DM / 4)
#define N4W (DM * DM / 4)

__global__ void round_all(
    const float* __restrict__ Q, const float* __restrict__ K, const float* __restrict__ V,
    const float* __restrict__ Wq, const float* __restrict__ Wk,
    const float* __restrict__ Wv, const float* __restrict__ Wo,
    float* qo, float* ko, float* vo, float* wqo, float* wko, float* wvo, float* woo)
{
    int i = blockIdx.x * blockDim.x + threadIdx.x;
    const float4* s;
    float4* d;
    int off;
    if (i < 3 * N4I) {
        int seg = i / N4I;
        off = i - seg * N4I;
        s = (const float4*)(seg == 0 ? Q : seg == 1 ? K : V);
        d = (float4*)(seg == 0 ? qo : seg == 1 ? ko : vo);
    } else {
        int j = i - 3 * N4I;
        int seg = j / N4W;
        off = j - seg * N4W;
        s = (const float4*)(seg == 0 ? Wq : seg == 1 ? Wk : seg == 2 ? Wv : Wo);
        d = (float4*)(seg == 0 ? wqo : seg == 1 ? wko : seg == 2 ? wvo : woo);
    }
    float4 v = s[off];
    v.x = f2tf32f(v.x); v.y = f2tf32f(v.y);
    v.z = f2tf32f(v.z); v.w = f2tf32f(v.w);
    d[off] = v;
}

// ---------------- TF32 GEMM (mma.sync, cp.async 3-stage pipeline) ----------------
// C[8192,1024] = A[8192,1024(K-major)] @ W[1024,1024(K-major)]^T + bias
// gridDim.z selects (A, W, bias, out) so independent GEMMs share one launch.
// mode 0: scatter into [B,H,S,Dh] tf32-rounded; z<2 (Q,K) additionally applies
//         perm8 on the Dh low bits. mode 1: row-major [T,N] raw.
#define GSTAGE_BYTES 32768
#define GSMEM        (3 * GSTAGE_BYTES)   // 98304

struct GArgs {
    const float* A[3];
    const float* W[3];
    const float* bias[3];
    float* out[3];
    int mode;
};

__global__ void __launch_bounds__(256, 2)
gemm_ms(GArgs ga)
{
    extern __shared__ char smc[];
    const uint32_t sb = smem_u32(smc);
    const int z = blockIdx.z;
    const float* __restrict__ A    = ga.A[z];
    const float* __restrict__ W    = ga.W[z];
    const float* __restrict__ bias = ga.bias[z];
    float* __restrict__ out        = ga.out[z];
    const int mode = ga.mode;
    const bool do_perm = (mode == 0) && (z < 2);

    const int tid  = threadIdx.x;
    const int warp = tid >> 5, lane = tid & 31;
    const int g = lane >> 2, t = lane & 3;
    const int wm = warp >> 2, wn = warp & 3;
    const int bm = blockIdx.y * 128, bn = blockIdx.x * 128;

    const float* Ab = A + (size_t)bm * DM;
    const float* Wb = W + (size_t)bn * DM;

    float acc[4][4][4];
#pragma unroll
    for (int i = 0; i < 4; i++)
#pragma unroll
        for (int j = 0; j < 4; j++)
#pragma unroll
            for (int e = 0; e < 4; e++) acc[i][j][e] = 0.f;

#define LOAD_TILE(kt, stg)                                                       \
    do {                                                                         \
        uint32_t bA = sb + (stg) * GSTAGE_BYTES;                                 \
        uint32_t bBs = bA + 16384;                                               \
        int kc = (kt) * 32;                                                      \
        _Pragma("unroll")                                                        \
        for (int i_ = 0; i_ < 4; i_++) {                                         \
            int id = tid + i_ * 256;                                             \
            int r_ = id >> 3, c4 = id & 7;                                       \
            uint32_t doff = (uint32_t)(r_ * 128 + ((c4 ^ (r_ & 7)) << 4));       \
            cpasync16(bA + doff,  Ab + (size_t)r_ * DM + kc + c4 * 4);           \
            cpasync16(bBs + doff, Wb + (size_t)r_ * DM + kc + c4 * 4);           \
        }                                                                        \
    } while (0)

    LOAD_TILE(0, 0); CP_COMMIT();
    LOAD_TILE(1, 1); CP_COMMIT();
    LOAD_TILE(2, 2); CP_COMMIT();

    for (int tt = 0; tt < 32; tt++) {
        CP_WAIT(2);
        __syncthreads();
        const int stg = tt % 3;
        const float* sA = (const float*)(smc + stg * GSTAGE_BYTES);
        const float* sB = sA + 4096;
#pragma unroll
        for (int k8 = 0; k8 < 4; k8++) {
            const int ch0 = (((k8 * 2)     ^ g) & 7) << 2;
            const int ch1 = (((k8 * 2 + 1) ^ g) & 7) << 2;
            uint32_t af[4][4], bf[4][2];
#pragma unroll
            for (int i = 0; i < 4; i++) {
                int r0 = (wm * 64 + i * 16 + g) * 32;
                af[i][0] = __float_as_uint(sA[r0 + ch0 + t]);
                af[i][1] = __float_as_uint(sA[r0 + 256 + ch0 + t]);
                af[i][2] = __float_as_uint(sA[r0 + ch1 + t]);
                af[i][3] = __float_as_uint(sA[r0 + 256 + ch1 + t]);
            }
#pragma unroll
            for (int j = 0; j < 4; j++) {
                int n0 = (wn * 32 + j * 8 + g) * 32;
                bf[j][0] = __float_as_uint(sB[n0 + ch0 + t]);
                bf[j][1] = __float_as_uint(sB[n0 + ch1 + t]);
            }
#pragma unroll
            for (int i = 0; i < 4; i++)
#pragma unroll
                for (int j = 0; j < 4; j++) mma8(acc[i][j], af[i], bf[j]);
        }
        __syncthreads();
        if (tt + 3 < 32) LOAD_TILE(tt + 3, (tt + 3) % 3);
        CP_COMMIT();
    }
#undef LOAD_TILE

    // epilogue
#pragma unroll
    for (int i = 0; i < 4; i++) {
#pragma unroll
        for (int j = 0; j < 4; j++) {
            int row0 = bm + wm * 64 + i * 16 + g;
            int col0 = bn + wn * 32 + j * 8 + 2 * t;
            float b0 = bias[col0], b1 = bias[col0 + 1];
            if (mode == 1) {
                out[(size_t)row0 * DM + col0]           = acc[i][j][0] + b0;
                out[(size_t)row0 * DM + col0 + 1]       = acc[i][j][1] + b1;
                out[(size_t)(row0 + 8) * DM + col0]     = acc[i][j][2] + b0;
                out[(size_t)(row0 + 8) * DM + col0 + 1] = acc[i][j][3] + b1;
            } else {
                // scatter into [B,H,S,Dh], tf32-rounded; Q/K get Dh pair-perm
                int c0 = col0, c1 = col0 + 1;
                int dh0 = c0 & 63, dh1 = c1 & 63;
                if (do_perm) {
                    dh0 = (dh0 & ~7) | perm8(dh0 & 7);
                    dh1 = (dh1 & ~7) | perm8(dh1 & 7);
                }
                int h = c0 >> 6;                 // c0,c1 same head (col0 even)
                int b = row0 >> 11, s = row0 & 2047;
                size_t hb = (((size_t)b * NH + h) * SS);
                size_t r0b = (hb + s) * DH;
                size_t r1b = r0b + 8 * DH;       // row0+8, same b
                out[r0b + dh0] = f2tf32f(acc[i][j][0] + b0);
                out[r0b + dh1] = f2tf32f(acc[i][j][1] + b1);
                out[r1b + dh0] = f2tf32f(acc[i][j][2] + b0);
                out[r1b + dh1] = f2tf32f(acc[i][j][3] + b1);
            }
        }
    }
}

// ---------------- Flash attention (TF32 mma.sync), double-buffered cp.async ----------------
// g_q / g_k have the Dh pair-permutation -> K fragments load as LDS.64,
// Q fragments as float2. V / P paths use natural kv order.
#define KSP 68   // 272B rows; row*68 ≡ 4*row (mod 32) -> 4g+2t distinct, .64 conflict-free
#define VSP 72
#define PSP 132
#define BUF_FLOATS (128 * (KSP + VSP))           // 17920
#define ATTN_SMEM_FLOATS (2 * BUF_FLOATS + 128 * PSP)
#define ATTN_SMEM_BYTES  (ATTN_SMEM_FLOATS * 4)  // 210944

__global__ void __launch_bounds__(256, 1)
attn_kernel(const float* __restrict__ q, const float* __restrict__ k,
            const float* __restrict__ v, float* __restrict__ out)
{
    extern __shared__ float sm[];
    const uint32_t sba = smem_u32(sm);
    float* Ps = sm + 2 * BUF_FLOATS;

    const int tid = threadIdx.x, warp = tid >> 5, lane = tid & 31;
    const int g = lane >> 2, t = lane & 3;
    const int bh = blockIdx.y, qt = blockIdx.x;
    const int band = warp * 16;

    const float* qb = q + (size_t)bh * SS * DH;
    const float* kb = k + (size_t)bh * SS * DH;
    const float* vb = v + (size_t)bh * SS * DH;

#define AFILL(tile, buf)                                                        \
    do {                                                                        \
        const float* kt_ = kb + (size_t)(tile) * 128 * DH;                      \
        const float* vt_ = vb + (size_t)(tile) * 128 * DH;                      \
        uint32_t kb_ = sba + (buf) * (BUF_FLOATS * 4);                          \
        uint32_t vb_ = kb_ + 128 * KSP * 4;                                     \
        _Pragma("unroll")                                                       \
        for (int i_ = 0; i_ < 8; i_++) {                                        \
            int id = tid + i_ * 256;                                            \
            int r_ = id >> 4, c_ = id & 15;                                     \
            cpasync16(kb_ + r_ * 272 + c_ * 16, kt_ + r_ * 64 + c_ * 4);        \
            cpasync16(vb_ + r_ * 288 + c_ * 16, vt_ + r_ * 64 + c_ * 4);        \
        }                                                                       \
    } while (0)

    const float qscale = 0.125f * 1.4426950408889634f;

    // Q fragments: permuted layout -> cols (t, t+4) at slots (2t, 2t+1): float2
    uint32_t qf[8][4];
    {
        int r0 = qt * 128 + band + g;
        const float* q0 = qb + (size_t)r0 * DH;
        const float* q1 = qb + (size_t)(r0 + 8) * DH;
#pragma unroll
        for (int kk = 0; kk < 8; kk++) {
            int c = kk * 8 + 2 * t;
            float2 a = *(const float2*)(q0 + c);
            float2 b2 = *(const float2*)(q1 + c);
            qf[kk][0] = f2tf32(a.x * qscale);
            qf[kk][2] = f2tf32(a.y * qscale);
            qf[kk][1] = f2tf32(b2.x * qscale);
            qf[kk][3] = f2tf32(b2.y * qscale);
        }
    }

    float m0 = -INFINITY, m1 = -INFINITY, l0 = 0.f, l1 = 0.f;
    float oa[8][4];
#pragma unroll
    for (int j = 0; j < 8; j++)
#pragma unroll
        for (int e = 0; e < 4; e++) oa[j][e] = 0.f;

    float* prow0 = Ps + (band + g) * PSP;
    float* prow1 = Ps + (band + g + 8) * PSP;

    AFILL(0, 0); CP_COMMIT();

    for (int kv = 0; kv < 16; kv++) {
        if (kv < 15) { AFILL(kv + 1, (kv + 1) & 1); CP_COMMIT(); CP_WAIT(1); }
        else         { CP_WAIT(0); }
        __syncthreads();

        const float* Ks = sm + (kv & 1) * BUF_FLOATS;
        const float* Vs = Ks + 128 * KSP;

        // S = Q * K^T : K fragments via LDS.64 (permuted cols)
        float sf[16][4];
#pragma unroll
        for (int j = 0; j < 16; j++)
#pragma unroll
            for (int e = 0; e < 4; e++) sf[j][e] = 0.f;
#pragma unroll
        for (int kk = 0; kk < 8; kk++) {
            const int co = kk * 8 + 2 * t;
#pragma unroll
            for (int j = 0; j < 16; j++) {
                float2 kp = *(const float2*)(Ks + (j * 8 + g) * KSP + co);
                uint32_t bbf[2];
                bbf[0] = __float_as_uint(kp.x);
                bbf[1] = __float_as_uint(kp.y);
                mma8(sf[j], qf[kk], bbf);
            }
        }

        // online softmax
        float mt0 = -INFINITY, mt1 = -INFINITY;
#pragma unroll
        for (int j = 0; j < 16; j++) {
            mt0 = fmaxf(mt0, fmaxf(sf[j][0], sf[j][1]));
            mt1 = fmaxf(mt1, fmaxf(sf[j][2], sf[j][3]));
        }
        mt0 = fmaxf(mt0, __shfl_xor_sync(0xffffffffu, mt0, 1));
        mt0 = fmaxf(mt0, __shfl_xor_sync(0xffffffffu, mt0, 2));
        mt1 = fmaxf(mt1, __shfl_xor_sync(0xffffffffu, mt1, 1));
        mt1 = fmaxf(mt1, __shfl_xor_sync(0xffffffffu, mt1, 2));

        float mn0 = fmaxf(m0, mt0), mn1 = fmaxf(m1, mt1);
        float al0 = exp2f(m0 - mn0), al1 = exp2f(m1 - mn1);

        float rs0 = 0.f, rs1 = 0.f;
#pragma unroll
        for (int j = 0; j < 16; j++) {
            float p0 = exp2f(sf[j][0] - mn0);
            float p1 = exp2f(sf[j][1] - mn0);
            float p2 = exp2f(sf[j][2] - mn1);
            float p3 = exp2f(sf[j][3] - mn1);
            rs0 += p0 + p1;
            rs1 += p2 + p3;
            int c0 = j * 8 + 2 * t;
            prow0[c0]     = f2tf32f(p0);
            prow0[c0 + 1] = f2tf32f(p1);
            prow1[c0]     = f2tf32f(p2);
            prow1[c0 + 1] = f2tf32f(p3);
        }
        rs0 += __shfl_xor_sync(0xffffffffu, rs0, 1);
        rs0 += __shfl_xor_sync(0xffffffffu, rs0, 2);
        rs1 += __shfl_xor_sync(0xffffffffu, rs1, 1);
        rs1 += __shfl_xor_sync(0xffffffffu, rs1, 2);

        l0 = l0 * al0 + rs0;
        l1 = l1 * al1 + rs1;
        m0 = mn0;
        m1 = mn1;
#pragma unroll
        for (int j = 0; j < 8; j++) {
            oa[j][0] *= al0; oa[j][1] *= al0;
            oa[j][2] *= al1; oa[j][3] *= al1;
        }
        __syncwarp();

        // O += P * V  (natural kv order)
#pragma unroll
        for (int kk = 0; kk < 16; kk++) {
            uint32_t af[4];
            af[0] = __float_as_uint(prow0[kk * 8 + t]);
            af[1] = __float_as_uint(prow1[kk * 8 + t]);
            af[2] = __float_as_uint(prow0[kk * 8 + t + 4]);
            af[3] = __float_as_uint(prow1[kk * 8 + t + 4]);
#pragma unroll
            for (int j = 0; j < 8; j++) {
                uint32_t bbf[2];
                bbf[0] = __float_as_uint(Vs[(kk * 8 + t) * VSP + j * 8 + g]);
                bbf[1] = __float_as_uint(Vs[(kk * 8 + t + 4) * VSP + j * 8 + g]);
                mma8(oa[j], af, bbf);
            }
        }
        __syncthreads();
    }
#undef AFILL

    float i0 = 1.f / l0, i1 = 1.f / l1;
    int b = bh >> 4, h = bh & 15;
    int tr0 = b * SS + qt * 128 + band + g;
    float* ob0 = out + (size_t)tr0 * DM + h * DH;
    float* ob1 = out + (size_t)(tr0 + 8) * DM + h * DH;
#pragma unroll
    for (int j = 0; j < 8; j++) {
        int c = j * 8 + 2 * t;
        ob0[c]     = f2tf32f(oa[j][0] * i0);
        ob0[c + 1] = f2tf32f(oa[j][1] * i0);
        ob1[c]     = f2tf32f(oa[j][2] * i1);
        ob1[c + 1] = f2tf32f(oa[j][3] * i1);
    }
}

// ---------------- launcher ----------------
extern "C" void kernel_launch(void* const* d_in, const int* in_sizes, int n_in,
                              void* d_out, int out_size)
{
    const float* Q  = (const float*)d_in[0];
    const float* K  = (const float*)d_in[1];
    const float* V  = (const float*)d_in[2];
    const float* Wq = (const float*)d_in[3];
    const float* bq = (const float*)d_in[4];
    const float* Wk = (const float*)d_in[5];
    const float* bk = (const float*)d_in[6];
    const float* Wv = (const float*)d_in[7];
    const float* bv = (const float*)d_in[8];
    const float* Wo = (const float*)d_in[9];
    const float* bo = (const float*)d_in[10];

    float *qp, *kp, *vp, *ap, *qi, *ki, *vi, *wq, *wk, *wv, *wo;
    cudaGetSymbolAddress((void**)&qp, g_q);
    cudaGetSymbolAddress((void**)&kp, g_k);
    cudaGetSymbolAddress((void**)&vp, g_v);
    cudaGetSymbolAddress((void**)&ap, g_attn);
    cudaGetSymbolAddress((void**)&qi, g_qin);
    cudaGetSymbolAddress((void**)&ki, g_kin);
    cudaGetSymbolAddress((void**)&vi, g_vin);
    cudaGetSymbolAddress((void**)&wq, g_wq);
    cudaGetSymbolAddress((void**)&wk, g_wk);
    cudaGetSymbolAddress((void**)&wv, g_wv);
    cudaGetSymbolAddress((void**)&wo, g_wo);

    cudaFuncSetAttribute(attn_kernel, cudaFuncAttributeMaxDynamicSharedMemorySize,
                         ATTN_SMEM_BYTES);
    cudaFuncSetAttribute(gemm_ms, cudaFuncAttributeMaxDynamicSharedMemorySize, GSMEM);

    // fused RNA rounding (one launch for 3 inputs + 4 weights)
    const int total4 = 3 * N4I + 4 * N4W;
    round_all<<<total4 / 256, 256>>>(Q, K, V, Wq, Wk, Wv, Wo,
                                     qi, ki, vi, wq, wk, wv, wo);

    // merged Q/K/V projection GEMMs (z = 0,1,2)
    GArgs gp;
    gp.A[0] = qi; gp.A[1] = ki; gp.A[2] = vi;
    gp.W[0] = wq; gp.W[1] = wk; gp.W[2] = wv;
    gp.bias[0] = bq; gp.bias[1] = bk; gp.bias[2] = bv;
    gp.out[0] = qp; gp.out[1] = kp; gp.out[2] = vp;
    gp.mode = 0;
    dim3 ggrid(DM / 128, TOK / 128, 3);   // (8, 64, 3)
    gemm_ms<<<ggrid, 256, GSMEM>>>(gp);

    dim3 agrid(SS / 128, BB * NH);        // (16, 64)
    attn_kernel<<<agrid, 256, ATTN_SMEM_BYTES>>>(qp, kp, vp, ap);

    // output projection
    GArgs go;
    go.A[0] = ap; go.A[1] = ap; go.A[2] = ap;
    go.W[0] = wo; go.W[1] = wo; go.W[2] = wo;
    go.bias[0] = bo; go.bias[1] = bo; go.bias[2] = bo;
    go.out[0] = (float*)d_out; go.out[1] = (float*)d_out; go.out[2] = (float*)d_out;
    go.mode = 1;
    dim3 ogrid(DM / 128, TOK / 128, 1);
    gemm_ms<<<ogrid, 256, GSMEM>>>(go);
}

// round 9
// speedup vs baseline: 1.0004x; 1.0004x over previous
#include <cuda_runtime.h>
#include <cstdint>

// Problem constants
#define BB    4
#define SS    2048
#define DM    1024
#define NH    16
#define DH    64
#define TOK   (BB * SS)          // 8192 tokens

// ---------------- scratch (no cudaMalloc allowed) ----------------
__device__ float g_q[TOK * DM];     // [B,H,S,Dh]  tf32, Dh PAIR-PERMUTED
__device__ float g_k[TOK * DM];     // [B,H,S,Dh]  tf32, Dh PAIR-PERMUTED
__device__ float g_v[TOK * DM];     // [B,H,S,Dh]  tf32, natural order
__device__ float g_attn[TOK * DM];  // [B,S,D]     tf32-rounded by attn epilogue

// ---------------- helpers ----------------
__device__ __forceinline__ uint32_t f2tf32(float x) {
    uint32_t u;
    asm("cvt.rna.tf32.f32 %0, %1;" : "=r"(u) : "f"(x));
    return u;
}
__device__ __forceinline__ float f2tf32f(float x) {
    return __uint_as_float(f2tf32(x));
}
__device__ __forceinline__ float ex2(float x) {
    float y;
    asm("ex2.approx.ftz.f32 %0, %1;" : "=f"(y) : "f"(x));
    return y;
}

__device__ __forceinline__ uint32_t smem_u32(const void* p) {
    uint32_t a;
    asm("{ .reg .u64 t; cvta.to.shared.u64 t, %1; cvt.u32.u64 %0, t; }" : "=r"(a) : "l"(p));
    return a;
}

__device__ __forceinline__ void cpasync16(uint32_t dst, const void* src) {
    asm volatile("cp.async.cg.shared.global [%0], [%1], 16;" :: "r"(dst), "l"(src));
}
#define CP_COMMIT()  asm volatile("cp.async.commit_group;" ::: "memory")
#define CP_WAIT(n)   asm volatile("cp.async.wait_group " #n ";" ::: "memory")

__device__ __forceinline__ void mma8(float* c, const uint32_t* a, const uint32_t* b) {
    asm volatile(
        "mma.sync.aligned.m16n8k8.row.col.f32.tf32.tf32.f32 "
        "{%0,%1,%2,%3},{%4,%5,%6,%7},{%8,%9},{%0,%1,%2,%3};\n"
        : "+f"(c[0]), "+f"(c[1]), "+f"(c[2]), "+f"(c[3])
        : "r"(a[0]), "r"(a[1]), "r"(a[2]), "r"(a[3]),
          "r"(b[0]), "r"(b[1]));
}

// pair-permutation within 8-group: (0..3) -> even slots, (4..7) -> odd slots
__device__ __forceinline__ int perm8(int a) { return (a < 4) ? 2 * a : 2 * a - 7; }

// ---------------- TF32 GEMM (mma.sync, cp.async, distance-2, one sync/iter) ----------------
// C[8192,1024] = A[8192,1024(K-major)] @ W[1024,1024(K-major)]^T + bias
// Raw fp32 operands; cvt.rna.tf32 applied at fragment build (bit-identical to a
// gmem pre-rounding pass, without the extra 224MB of traffic).
// gridDim.z selects (A, W, bias, out). mode 0: scatter [B,H,S,Dh] tf32-rounded,
// z<2 applies perm8 to Dh low bits. mode 1: row-major [T,N] raw.
#define GSTAGE_BYTES 32768
#define GSMEM        (3 * GSTAGE_BYTES)   // 98304

struct GArgs {
    const float* A[3];
    const float* W[3];
    const float* bias[3];
    float* out[3];
    int mode;
};

__global__ void __launch_bounds__(256, 2)
gemm_ms(GArgs ga)
{
    extern __shared__ char smc[];
    const uint32_t sb = smem_u32(smc);
    const int z = blockIdx.z;
    const float* __restrict__ A    = ga.A[z];
    const float* __restrict__ W    = ga.W[z];
    const float* __restrict__ bias = ga.bias[z];
    float* __restrict__ out        = ga.out[z];
    const int mode = ga.mode;
    const bool do_perm = (mode == 0) && (z < 2);

    const int tid  = threadIdx.x;
    const int warp = tid >> 5, lane = tid & 31;
    const int g = lane >> 2, t = lane & 3;
    const int wm = warp >> 2, wn = warp & 3;
    const int bm = blockIdx.y * 128, bn = blockIdx.x * 128;

    const float* Ab = A + (size_t)bm * DM;
    const float* Wb = W + (size_t)bn * DM;

    float acc[4][4][4];
#pragma unroll
    for (int i = 0; i < 4; i++)
#pragma unroll
        for (int j = 0; j < 4; j++)
#pragma unroll
            for (int e = 0; e < 4; e++) acc[i][j][e] = 0.f;

#define LOAD_TILE(kt, stg)                                                       \
    do {                                                                         \
        uint32_t bA = sb + (stg) * GSTAGE_BYTES;                                 \
        uint32_t bBs = bA + 16384;                                               \
        int kc = (kt) * 32;                                                      \
        _Pragma("unroll")                                                        \
        for (int i_ = 0; i_ < 4; i_++) {                                         \
            int id = tid + i_ * 256;                                             \
            int r_ = id >> 3, c4 = id & 7;                                       \
            uint32_t doff = (uint32_t)(r_ * 128 + ((c4 ^ (r_ & 7)) << 4));       \
            cpasync16(bA + doff,  Ab + (size_t)r_ * DM + kc + c4 * 4);           \
            cpasync16(bBs + doff, Wb + (size_t)r_ * DM + kc + c4 * 4);           \
        }                                                                        \
    } while (0)

    LOAD_TILE(0, 0); CP_COMMIT();
    LOAD_TILE(1, 1); CP_COMMIT();

    for (int tt = 0; tt < 32; tt++) {
        if (tt < 31) { CP_WAIT(1); } else { CP_WAIT(0); }
        __syncthreads();
        if (tt + 2 < 32) { LOAD_TILE(tt + 2, (tt + 2) % 3); CP_COMMIT(); }

        const int stg = tt % 3;
        const float* sA = (const float*)(smc + stg * GSTAGE_BYTES);
        const float* sB = sA + 4096;
#pragma unroll
        for (int k8 = 0; k8 < 4; k8++) {
            const int ch0 = (((k8 * 2)     ^ g) & 7) << 2;
            const int ch1 = (((k8 * 2 + 1) ^ g) & 7) << 2;
            uint32_t af[4][4], bf[4][2];
#pragma unroll
            for (int i = 0; i < 4; i++) {
                int r0 = (wm * 64 + i * 16 + g) * 32;
                af[i][0] = f2tf32(sA[r0 + ch0 + t]);
                af[i][1] = f2tf32(sA[r0 + 256 + ch0 + t]);
                af[i][2] = f2tf32(sA[r0 + ch1 + t]);
                af[i][3] = f2tf32(sA[r0 + 256 + ch1 + t]);
            }
#pragma unroll
            for (int j = 0; j < 4; j++) {
                int n0 = (wn * 32 + j * 8 + g) * 32;
                bf[j][0] = f2tf32(sB[n0 + ch0 + t]);
                bf[j][1] = f2tf32(sB[n0 + ch1 + t]);
            }
#pragma unroll
            for (int i = 0; i < 4; i++)
#pragma unroll
                for (int j = 0; j < 4; j++) mma8(acc[i][j], af[i], bf[j]);
        }
    }
#undef LOAD_TILE

    // epilogue
#pragma unroll
    for (int i = 0; i < 4; i++) {
#pragma unroll
        for (int j = 0; j < 4; j++) {
            int row0 = bm + wm * 64 + i * 16 + g;
            int col0 = bn + wn * 32 + j * 8 + 2 * t;
            float b0 = bias[col0], b1 = bias[col0 + 1];
            if (mode == 1) {
                out[(size_t)row0 * DM + col0]           = acc[i][j][0] + b0;
                out[(size_t)row0 * DM + col0 + 1]       = acc[i][j][1] + b1;
                out[(size_t)(row0 + 8) * DM + col0]     = acc[i][j][2] + b0;
                out[(size_t)(row0 + 8) * DM + col0 + 1] = acc[i][j][3] + b1;
            } else {
                int c0 = col0, c1 = col0 + 1;
                int dh0 = c0 & 63, dh1 = c1 & 63;
                if (do_perm) {
                    dh0 = (dh0 & ~7) | perm8(dh0 & 7);
                    dh1 = (dh1 & ~7) | perm8(dh1 & 7);
                }
                int h = c0 >> 6;
                int b = row0 >> 11, s = row0 & 2047;
                size_t hb = (((size_t)b * NH + h) * SS);
                size_t r0b = (hb + s) * DH;
                size_t r1b = r0b + 8 * DH;
                out[r0b + dh0] = f2tf32f(acc[i][j][0] + b0);
                out[r0b + dh1] = f2tf32f(acc[i][j][1] + b1);
                out[r1b + dh0] = f2tf32f(acc[i][j][2] + b0);
                out[r1b + dh1] = f2tf32f(acc[i][j][3] + b1);
            }
        }
    }
}

// ---------------- Flash attention (TF32 mma.sync), one sync per kv tile ----------------
#define KSP 68   // 272B rows; 4g+2t distinct mod 32 -> conflict-free float2
#define VSP 72
#define PSP 132
#define BUF_FLOATS (128 * (KSP + VSP))           // 17920
#define ATTN_SMEM_FLOATS (2 * BUF_FLOATS + 128 * PSP)
#define ATTN_SMEM_BYTES  (ATTN_SMEM_FLOATS * 4)  // 210944

__global__ void __launch_bounds__(256, 1)
attn_kernel(const float* __restrict__ q, const float* __restrict__ k,
            const float* __restrict__ v, float* __restrict__ out)
{
    extern __shared__ float sm[];
    const uint32_t sba = smem_u32(sm);
    float* Ps = sm + 2 * BUF_FLOATS;

    const int tid = threadIdx.x, warp = tid >> 5, lane = tid & 31;
    const int g = lane >> 2, t = lane & 3;
    const int bh = blockIdx.y, qt = blockIdx.x;
    const int band = warp * 16;

    const float* qb = q + (size_t)bh * SS * DH;
    const float* kb = k + (size_t)bh * SS * DH;
    const float* vb = v + (size_t)bh * SS * DH;

#define AFILL(tile, buf)                                                        \
    do {                                                                        \
        const float* kt_ = kb + (size_t)(tile) * 128 * DH;                      \
        const float* vt_ = vb + (size_t)(tile) * 128 * DH;                      \
        uint32_t kb_ = sba + (buf) * (BUF_FLOATS * 4);                          \
        uint32_t vb_ = kb_ + 128 * KSP * 4;                                     \
        _Pragma("unroll")                                                       \
        for (int i_ = 0; i_ < 8; i_++) {                                        \
            int id = tid + i_ * 256;                                            \
            int r_ = id >> 4, c_ = id & 15;                                     \
            cpasync16(kb_ + r_ * 272 + c_ * 16, kt_ + r_ * 64 + c_ * 4);        \
            cpasync16(vb_ + r_ * 288 + c_ * 16, vt_ + r_ * 64 + c_ * 4);        \
        }                                                                       \
    } while (0)

    AFILL(0, 0); CP_COMMIT();

    const float qscale = 0.125f * 1.4426950408889634f;

    // Q fragments: permuted layout -> cols (t, t+4) at slots (2t, 2t+1): float2
    uint32_t qf[8][4];
    {
        int r0 = qt * 128 + band + g;
        const float* q0 = qb + (size_t)r0 * DH;
        const float* q1 = qb + (size_t)(r0 + 8) * DH;
#pragma unroll
        for (int kk = 0; kk < 8; kk++) {
            int c = kk * 8 + 2 * t;
            float2 a = *(const float2*)(q0 + c);
            float2 b2 = *(const float2*)(q1 + c);
            qf[kk][0] = f2tf32(a.x * qscale);
            qf[kk][2] = f2tf32(a.y * qscale);
            qf[kk][1] = f2tf32(b2.x * qscale);
            qf[kk][3] = f2tf32(b2.y * qscale);
        }
    }

    float m0 = -INFINITY, m1 = -INFINITY, l0 = 0.f, l1 = 0.f;
    float oa[8][4];
#pragma unroll
    for (int j = 0; j < 8; j++)
#pragma unroll
        for (int e = 0; e < 4; e++) oa[j][e] = 0.f;

    float* prow0 = Ps + (band + g) * PSP;
    float* prow1 = Ps + (band + g + 8) * PSP;

    for (int kv = 0; kv < 16; kv++) {
        CP_WAIT(0);            // tile kv resident (per-thread)
        __syncthreads();       // all threads' parts visible; prev-prev buf free
        if (kv < 15) { AFILL(kv + 1, (kv + 1) & 1); CP_COMMIT(); }

        const float* Ks = sm + (kv & 1) * BUF_FLOATS;
        const float* Vs = Ks + 128 * KSP;

        // S = Q * K^T  (log2-domain logits); K fragments via float2
        float sf[16][4];
#pragma unroll
        for (int j = 0; j < 16; j++)
#pragma unroll
            for (int e = 0; e < 4; e++) sf[j][e] = 0.f;
#pragma unroll
        for (int kk = 0; kk < 8; kk++) {
            const int co = kk * 8 + 2 * t;
#pragma unroll
            for (int j = 0; j < 16; j++) {
                float2 kp = *(const float2*)(Ks + (j * 8 + g) * KSP + co);
                uint32_t bbf[2];
                bbf[0] = __float_as_uint(kp.x);
                bbf[1] = __float_as_uint(kp.y);
                mma8(sf[j], qf[kk], bbf);
            }
        }

        // online softmax
        float mt0 = -INFINITY, mt1 = -INFINITY;
#pragma unroll
        for (int j = 0; j < 16; j++) {
            mt0 = fmaxf(mt0, fmaxf(sf[j][0], sf[j][1]));
            mt1 = fmaxf(mt1, fmaxf(sf[j][2], sf[j][3]));
        }
        mt0 = fmaxf(mt0, __shfl_xor_sync(0xffffffffu, mt0, 1));
        mt0 = fmaxf(mt0, __shfl_xor_sync(0xffffffffu, mt0, 2));
        mt1 = fmaxf(mt1, __shfl_xor_sync(0xffffffffu, mt1, 1));
        mt1 = fmaxf(mt1, __shfl_xor_sync(0xffffffffu, mt1, 2));

        float mn0 = fmaxf(m0, mt0), mn1 = fmaxf(m1, mt1);
        float al0 = ex2(m0 - mn0), al1 = ex2(m1 - mn1);

        float rs0 = 0.f, rs1 = 0.f;
#pragma unroll
        for (int j = 0; j < 16; j++) {
            float p0 = ex2(sf[j][0] - mn0);
            float p1 = ex2(sf[j][1] - mn0);
            float p2 = ex2(sf[j][2] - mn1);
            float p3 = ex2(sf[j][3] - mn1);
            rs0 += p0 + p1;
            rs1 += p2 + p3;
            int c0 = j * 8 + 2 * t;
            prow0[c0]     = f2tf32f(p0);
            prow0[c0 + 1] = f2tf32f(p1);
            prow1[c0]     = f2tf32f(p2);
            prow1[c0 + 1] = f2tf32f(p3);
        }
        rs0 += __shfl_xor_sync(0xffffffffu, rs0, 1);
        rs0 += __shfl_xor_sync(0xffffffffu, rs0, 2);
        rs1 += __shfl_xor_sync(0xffffffffu, rs1, 1);
        rs1 += __shfl_xor_sync(0xffffffffu, rs1, 2);

        l0 = l0 * al0 + rs0;
        l1 = l1 * al1 + rs1;
        m0 = mn0;
        m1 = mn1;
#pragma unroll
        for (int j = 0; j < 8; j++) {
            oa[j][0] *= al0; oa[j][1] *= al0;
            oa[j][2] *= al1; oa[j][3] *= al1;
        }
        __syncwarp();   // P rows are warp-private; cross-thread smem visibility

        // O += P * V
#pragma unroll
        for (int kk = 0; kk < 16; kk++) {
            uint32_t af[4];
            af[0] = __float_as_uint(prow0[kk * 8 + t]);
            af[1] = __float_as_uint(prow1[kk * 8 + t]);
            af[2] = __float_as_uint(prow0[kk * 8 + t + 4]);
            af[3] = __float_as_uint(prow1[kk * 8 + t + 4]);
#pragma unroll
            for (int j = 0; j < 8; j++) {
                uint32_t bbf[2];
                bbf[0] = __float_as_uint(Vs[(kk * 8 + t) * VSP + j * 8 + g]);
                bbf[1] = __float_as_uint(Vs[(kk * 8 + t + 4) * VSP + j * 8 + g]);
                mma8(oa[j], af, bbf);
            }
        }
        // no trailing sync: next iteration's top sync covers buffer reuse
    }
#undef AFILL

    float i0 = 1.f / l0, i1 = 1.f / l1;
    int b = bh >> 4, h = bh & 15;
    int tr0 = b * SS + qt * 128 + band + g;
    float* ob0 = out + (size_t)tr0 * DM + h * DH;
    float* ob1 = out + (size_t)(tr0 + 8) * DM + h * DH;
#pragma unroll
    for (int j = 0; j < 8; j++) {
        int c = j * 8 + 2 * t;
        ob0[c]     = f2tf32f(oa[j][0] * i0);
        ob0[c + 1] = f2tf32f(oa[j][1] * i0);
        ob1[c]     = f2tf32f(oa[j][2] * i1);
        ob1[c + 1] = f2tf32f(oa[j][3] * i1);
    }
}

// ---------------- launcher ----------------
extern "C" void kernel_launch(void* const* d_in, const int* in_sizes, int n_in,
                              void* d_out, int out_size)
{
    const float* Q  = (const float*)d_in[0];
    const float* K  = (const float*)d_in[1];
    const float* V  = (const float*)d_in[2];
    const float* Wq = (const float*)d_in[3];
    const float* bq = (const float*)d_in[4];
    const float* Wk = (const float*)d_in[5];
    const float* bk = (const float*)d_in[6];
    const float* Wv = (const float*)d_in[7];
    const float* bv = (const float*)d_in[8];
    const float* Wo = (const float*)d_in[9];
    const float* bo = (const float*)d_in[10];

    float *qp, *kp, *vp, *ap;
    cudaGetSymbolAddress((void**)&qp, g_q);
    cudaGetSymbolAddress((void**)&kp, g_k);
    cudaGetSymbolAddress((void**)&vp, g_v);
    cudaGetSymbolAddress((void**)&ap, g_attn);

    cudaFuncSetAttribute(attn_kernel, cudaFuncAttributeMaxDynamicSharedMemorySize,
                         ATTN_SMEM_BYTES);
    cudaFuncSetAttribute(gemm_ms, cudaFuncAttributeMaxDynamicSharedMemorySize, GSMEM);

    // merged Q/K/V projection GEMMs (z = 0,1,2) — raw inputs, in-kernel tf32 cvt
    GArgs gp;
    gp.A[0] = Q;  gp.A[1] = K;  gp.A[2] = V;
    gp.W[0] = Wq; gp.W[1] = Wk; gp.W[2] = Wv;
    gp.bias[0] = bq; gp.bias[1] = bk; gp.bias[2] = bv;
    gp.out[0] = qp; gp.out[1] = kp; gp.out[2] = vp;
    gp.mode = 0;
    dim3 ggrid(DM / 128, TOK / 128, 3);   // (8, 64, 3)
    gemm_ms<<<ggrid, 256, GSMEM>>>(gp);

    dim3 agrid(SS / 128, BB * NH);        // (16, 64)
    attn_kernel<<<agrid, 256, ATTN_SMEM_BYTES>>>(qp, kp, vp, ap);

    // output projection
    GArgs go;
    go.A[0] = ap; go.A[1] = ap; go.A[2] = ap;
    go.W[0] = Wo; go.W[1] = Wo; go.W[2] = Wo;
    go.bias[0] = bo; go.bias[1] = bo; go.bias[2] = bo;
    go.out[0] = (float*)d_out; go.out[1] = (float*)d_out; go.out[2] = (float*)d_out;
    go.mode = 1;
    dim3 ogrid(DM / 128, TOK / 128, 1);
    gemm_ms<<<ogrid, 256, GSMEM>>>(go);
}

// round 10
// speedup vs baseline: 1.8098x; 1.8092x over previous
#include <cuda_runtime.h>
#include <cuda_fp16.h>
#include <cstdint>

// Problem constants
#define BB    4
#define SS    2048
#define DM    1024
#define NH    16
#define DH    64
#define TOK   (BB * SS)          // 8192 tokens

// ---------------- scratch (no cudaMalloc allowed) ----------------
__device__ __half g_qh[TOK * DM];      // [B,H,S,Dh]
__device__ __half g_kh[TOK * DM];      // [B,H,S,Dh]
__device__ __half g_vth[TOK * DM];     // [B,H,Dh,S]  (V transposed)
__device__ __half g_ah[TOK * DM];      // [B,S,D]     attn output
__device__ __half g_xh[3 * TOK * DM];  // fp16 inputs Q,K,V
__device__ __half g_wh[4 * DM * DM];   // fp16 weights Wq,Wk,Wv,Wo

// ---------------- helpers ----------------
__device__ __forceinline__ uint32_t smem_u32(const void* p) {
    uint32_t a;
    asm("{ .reg .u64 t; cvta.to.shared.u64 t, %1; cvt.u32.u64 %0, t; }" : "=r"(a) : "l"(p));
    return a;
}
__device__ __forceinline__ float ex2(float x) {
    float y;
    asm("ex2.approx.ftz.f32 %0, %1;" : "=f"(y) : "f"(x));
    return y;
}
__device__ __forceinline__ void cpasync16(uint32_t dst, const void* src) {
    asm volatile("cp.async.cg.shared.global [%0], [%1], 16;" :: "r"(dst), "l"(src));
}
#define CP_COMMIT()  asm volatile("cp.async.commit_group;" ::: "memory")
#define CP_WAIT(n)   asm volatile("cp.async.wait_group " #n ";" ::: "memory")

__device__ __forceinline__ void mma16(float* c, const uint32_t* a, const uint32_t* b) {
    asm volatile(
        "mma.sync.aligned.m16n8k16.row.col.f32.f16.f16.f32 "
        "{%0,%1,%2,%3},{%4,%5,%6,%7},{%8,%9},{%0,%1,%2,%3};\n"
        : "+f"(c[0]), "+f"(c[1]), "+f"(c[2]), "+f"(c[3])
        : "r"(a[0]), "r"(a[1]), "r"(a[2]), "r"(a[3]),
          "r"(b[0]), "r"(b[1]));
}
__device__ __forceinline__ uint32_t h2u(__half2 h) {
    return *reinterpret_cast<uint32_t*>(&h);
}

// ---------------- fp32 -> fp16 conversion pass ----------------
#define N4I (TOK * DM / 4)
#define N4W (DM * DM / 4)

__global__ void cvt_all(const float* __restrict__ Q, const float* __restrict__ K,
                        const float* __restrict__ V,
                        const float* __restrict__ Wq, const float* __restrict__ Wk,
                        const float* __restrict__ Wv, const float* __restrict__ Wo)
{
    int i = blockIdx.x * blockDim.x + threadIdx.x;
    const float4* s;
    __half2* d;
    int off;
    if (i < 3 * N4I) {
        int seg = i / N4I;
        off = i - seg * N4I;
        s = (const float4*)(seg == 0 ? Q : seg == 1 ? K : V);
        d = (__half2*)(g_xh + (size_t)seg * TOK * DM);
    } else {
        int j = i - 3 * N4I;
        int seg = j / N4W;
        off = j - seg * N4W;
        s = (const float4*)(seg == 0 ? Wq : seg == 1 ? Wk : seg == 2 ? Wv : Wo);
        d = (__half2*)(g_wh + (size_t)seg * DM * DM);
    }
    float4 v = s[off];
    d[2 * off]     = __floats2half2_rn(v.x, v.y);
    d[2 * off + 1] = __floats2half2_rn(v.z, v.w);
}

// ---------------- fp16 GEMM (mma.sync m16n8k16, cp.async distance-2) ----------------
// C[8192,1024] = A[8192,1024(K-major)] @ W[1024,1024(K-major)]^T + bias
// smem rows: 32 halves = 64B data, pitch 80B -> bank-exhaustive (20g+t mod 32),
// conflict-free fragment loads without swizzle.
// mode 0: z=0/1 -> [B,H,S,Dh] fp16; z=2 -> V transposed [B,H,Dh,S] fp16.
// mode 1: fp32 row-major [T,N] (final output).
#define GP    80
#define GSTG  (128 * GP * 2)     // 20480 per stage (A then B)
#define GSMEM (3 * GSTG)         // 61440

struct GArgs {
    const __half* A[3];
    const __half* W[3];
    const float*  bias[3];
    void*         out[3];
    int mode;
};

__global__ void __launch_bounds__(256, 2)
gemm_h(GArgs ga)
{
    extern __shared__ char smc[];
    const uint32_t sb = smem_u32(smc);
    const int z = blockIdx.z;
    const __half* __restrict__ A   = ga.A[z];
    const __half* __restrict__ W   = ga.W[z];
    const float* __restrict__ bias = ga.bias[z];
    const int mode = ga.mode;

    const int tid  = threadIdx.x;
    const int warp = tid >> 5, lane = tid & 31;
    const int g = lane >> 2, t = lane & 3;
    const int wm = warp >> 2, wn = warp & 3;
    const int bm = blockIdx.y * 128, bn = blockIdx.x * 128;

    const __half* Ab = A + (size_t)bm * DM;
    const __half* Wb = W + (size_t)bn * DM;

    float acc[4][4][4];
#pragma unroll
    for (int i = 0; i < 4; i++)
#pragma unroll
        for (int j = 0; j < 4; j++)
#pragma unroll
            for (int e = 0; e < 4; e++) acc[i][j][e] = 0.f;

#define LOAD_TILE(kt, stg)                                                      \
    do {                                                                        \
        uint32_t bA = sb + (stg) * GSTG;                                        \
        uint32_t bB = bA + 128 * GP;                                            \
        int kc = (kt) * 32;                                                     \
        _Pragma("unroll")                                                       \
        for (int i_ = 0; i_ < 2; i_++) {                                        \
            int id = tid + i_ * 256;                                            \
            int r_ = id >> 2, c4 = id & 3;                                      \
            cpasync16(bA + r_ * GP + c4 * 16, Ab + (size_t)r_ * DM + kc + c4 * 8); \
            cpasync16(bB + r_ * GP + c4 * 16, Wb + (size_t)r_ * DM + kc + c4 * 8); \
        }                                                                       \
    } while (0)

    LOAD_TILE(0, 0); CP_COMMIT();
    LOAD_TILE(1, 1); CP_COMMIT();

    for (int tt = 0; tt < 32; tt++) {
        if (tt < 31) { CP_WAIT(1); } else { CP_WAIT(0); }
        __syncthreads();
        if (tt + 2 < 32) { LOAD_TILE(tt + 2, (tt + 2) % 3); CP_COMMIT(); }

        const char* sA = smc + (tt % 3) * GSTG;
        const char* sB = sA + 128 * GP;
#pragma unroll
        for (int s = 0; s < 2; s++) {
            uint32_t af[4][4], bf[4][2];
#pragma unroll
            for (int i = 0; i < 4; i++) {
                int ra = (wm * 64 + i * 16 + g) * GP + s * 32 + 4 * t;
                af[i][0] = *(const uint32_t*)(sA + ra);
                af[i][1] = *(const uint32_t*)(sA + ra + 8 * GP);
                af[i][2] = *(const uint32_t*)(sA + ra + 16);
                af[i][3] = *(const uint32_t*)(sA + ra + 8 * GP + 16);
            }
#pragma unroll
            for (int j = 0; j < 4; j++) {
                int rb = (wn * 32 + j * 8 + g) * GP + s * 32 + 4 * t;
                bf[j][0] = *(const uint32_t*)(sB + rb);
                bf[j][1] = *(const uint32_t*)(sB + rb + 16);
            }
#pragma unroll
            for (int i = 0; i < 4; i++)
#pragma unroll
                for (int j = 0; j < 4; j++) mma16(acc[i][j], af[i], bf[j]);
        }
    }
#undef LOAD_TILE

    // epilogue
#pragma unroll
    for (int i = 0; i < 4; i++) {
#pragma unroll
        for (int j = 0; j < 4; j++) {
            int row0 = bm + wm * 64 + i * 16 + g;
            int col0 = bn + wn * 32 + j * 8 + 2 * t;
            float b0 = bias[col0], b1 = bias[col0 + 1];
            float c00 = acc[i][j][0] + b0, c01 = acc[i][j][1] + b1;
            float c10 = acc[i][j][2] + b0, c11 = acc[i][j][3] + b1;
            if (mode == 1) {
                float* out = (float*)ga.out[z];
                out[(size_t)row0 * DM + col0]           = c00;
                out[(size_t)row0 * DM + col0 + 1]       = c01;
                out[(size_t)(row0 + 8) * DM + col0]     = c10;
                out[(size_t)(row0 + 8) * DM + col0 + 1] = c11;
            } else {
                __half* out = (__half*)ga.out[z];
                int h = col0 >> 6, dh0 = col0 & 63;
                int b = row0 >> 11, s = row0 & 2047;
                if (z < 2) {
                    // [B,H,S,Dh]: dh pair contiguous -> half2 stores
                    size_t base = (((size_t)(b * NH + h) * SS) + s) * DH + dh0;
                    *(__half2*)(out + base)          = __floats2half2_rn(c00, c01);
                    *(__half2*)(out + base + 8 * DH) = __floats2half2_rn(c10, c11);
                } else {
                    // V transposed [B,H,Dh,S]
                    size_t base = ((size_t)(b * NH + h) * DH + dh0) * SS + s;
                    out[base]          = __float2half_rn(c00);
                    out[base + SS]     = __float2half_rn(c01);
                    out[base + 8]      = __float2half_rn(c10);
                    out[base + SS + 8] = __float2half_rn(c11);
                }
            }
        }
    }
}

// ---------------- Flash attention (fp16 mma.sync m16n8k16) ----------------
// K smem [128 kv][64 dh] pitch 144B; V^T smem [64 dh][128 kv] pitch 272B;
// P smem [128 q][128 kv] fp16 pitch 272B. All fragment loads conflict-free
// (16r mod 128 row rotation + 4t lane spread).
#define KPIT   144
#define VPIT   272
#define PPIT   272
#define KBYTES (128 * KPIT)          // 18432
#define VBYTES (64 * VPIT)           // 17408
#define BUFB   (KBYTES + VBYTES)     // 35840
#define POFF   (2 * BUFB)            // 71680
#define ASMEM  (POFF + 128 * PPIT)   // 106496

__global__ void __launch_bounds__(256, 1)
attn_h(const __half* __restrict__ q, const __half* __restrict__ k,
       const __half* __restrict__ vt, __half* __restrict__ out)
{
    extern __shared__ char smc[];
    const uint32_t sba = smem_u32(smc);

    const int tid = threadIdx.x, warp = tid >> 5, lane = tid & 31;
    const int g = lane >> 2, t = lane & 3;
    const int bh = blockIdx.y, qt = blockIdx.x;
    const int band = warp * 16;

    const __half* qb  = q  + (size_t)bh * SS * DH;
    const __half* kb  = k  + (size_t)bh * SS * DH;
    const __half* vtb = vt + (size_t)bh * DH * SS;

#define AFILL(tile, buf)                                                            \
    do {                                                                            \
        uint32_t kb_ = sba + (buf) * BUFB;                                          \
        uint32_t vb_ = kb_ + KBYTES;                                                \
        _Pragma("unroll")                                                           \
        for (int i_ = 0; i_ < 4; i_++) {                                            \
            int id = tid + i_ * 256;                                                \
            int rk = id >> 3, ck = id & 7;                                          \
            cpasync16(kb_ + rk * KPIT + ck * 16,                                    \
                      kb + (size_t)((tile) * 128 + rk) * DH + ck * 8);              \
            int rv = id >> 4, cv = id & 15;                                         \
            cpasync16(vb_ + rv * VPIT + cv * 16,                                    \
                      vtb + (size_t)rv * SS + (tile) * 128 + cv * 8);               \
        }                                                                           \
    } while (0)

    AFILL(0, 0); CP_COMMIT();

    // Q fragments (4 k16-steps over Dh=64); natural fp16 layout -> direct half2
    uint32_t qf[4][4];
    {
        int r0 = qt * 128 + band + g;
        const __half* q0 = qb + (size_t)r0 * DH;
        const __half* q1 = q0 + 8 * DH;
#pragma unroll
        for (int s = 0; s < 4; s++) {
            qf[s][0] = *(const uint32_t*)(q0 + s * 16 + 2 * t);
            qf[s][1] = *(const uint32_t*)(q1 + s * 16 + 2 * t);
            qf[s][2] = *(const uint32_t*)(q0 + s * 16 + 2 * t + 8);
            qf[s][3] = *(const uint32_t*)(q1 + s * 16 + 2 * t + 8);
        }
    }

    const float SCL = 0.125f * 1.4426950408889634f;  // 1/sqrt(64) * log2(e)

    float m0 = -INFINITY, m1 = -INFINITY, l0 = 0.f, l1 = 0.f;
    float oa[8][4];
#pragma unroll
    for (int j = 0; j < 8; j++)
#pragma unroll
        for (int e = 0; e < 4; e++) oa[j][e] = 0.f;

    char* prow0 = smc + POFF + (band + g) * PPIT;
    char* prow1 = prow0 + 8 * PPIT;

    for (int kv = 0; kv < 16; kv++) {
        CP_WAIT(0);
        __syncthreads();
        if (kv < 15) { AFILL(kv + 1, (kv + 1) & 1); CP_COMMIT(); }

        const char* Ks = smc + (kv & 1) * BUFB;
        const char* Vt = Ks + KBYTES;

        // S = Q * K^T
        float sf[16][4];
#pragma unroll
        for (int j = 0; j < 16; j++)
#pragma unroll
            for (int e = 0; e < 4; e++) sf[j][e] = 0.f;
#pragma unroll
        for (int s = 0; s < 4; s++) {
#pragma unroll
            for (int j = 0; j < 16; j++) {
                int rb = (j * 8 + g) * KPIT + s * 32 + 4 * t;
                uint32_t bf[2];
                bf[0] = *(const uint32_t*)(Ks + rb);
                bf[1] = *(const uint32_t*)(Ks + rb + 16);
                mma16(sf[j], qf[s], bf);
            }
        }
        // apply softmax scale (log2 domain)
#pragma unroll
        for (int j = 0; j < 16; j++)
#pragma unroll
            for (int e = 0; e < 4; e++) sf[j][e] *= SCL;

        // online softmax
        float mt0 = -INFINITY, mt1 = -INFINITY;
#pragma unroll
        for (int j = 0; j < 16; j++) {
            mt0 = fmaxf(mt0, fmaxf(sf[j][0], sf[j][1]));
            mt1 = fmaxf(mt1, fmaxf(sf[j][2], sf[j][3]));
        }
        mt0 = fmaxf(mt0, __shfl_xor_sync(0xffffffffu, mt0, 1));
        mt0 = fmaxf(mt0, __shfl_xor_sync(0xffffffffu, mt0, 2));
        mt1 = fmaxf(mt1, __shfl_xor_sync(0xffffffffu, mt1, 1));
        mt1 = fmaxf(mt1, __shfl_xor_sync(0xffffffffu, mt1, 2));

        float mn0 = fmaxf(m0, mt0), mn1 = fmaxf(m1, mt1);
        float al0 = ex2(m0 - mn0), al1 = ex2(m1 - mn1);

        float rs0 = 0.f, rs1 = 0.f;
#pragma unroll
        for (int j = 0; j < 16; j++) {
            float p0 = ex2(sf[j][0] - mn0);
            float p1 = ex2(sf[j][1] - mn0);
            float p2 = ex2(sf[j][2] - mn1);
            float p3 = ex2(sf[j][3] - mn1);
            rs0 += p0 + p1;
            rs1 += p2 + p3;
            *(uint32_t*)(prow0 + 16 * j + 4 * t) = h2u(__floats2half2_rn(p0, p1));
            *(uint32_t*)(prow1 + 16 * j + 4 * t) = h2u(__floats2half2_rn(p2, p3));
        }
        rs0 += __shfl_xor_sync(0xffffffffu, rs0, 1);
        rs0 += __shfl_xor_sync(0xffffffffu, rs0, 2);
        rs1 += __shfl_xor_sync(0xffffffffu, rs1, 1);
        rs1 += __shfl_xor_sync(0xffffffffu, rs1, 2);

        l0 = l0 * al0 + rs0;
        l1 = l1 * al1 + rs1;
        m0 = mn0;
        m1 = mn1;
#pragma unroll
        for (int j = 0; j < 8; j++) {
            oa[j][0] *= al0; oa[j][1] *= al0;
            oa[j][2] *= al1; oa[j][3] *= al1;
        }
        __syncwarp();   // P rows warp-private

        // O += P * V   (V^T rows = dh, contiguous kv)
#pragma unroll
        for (int kk = 0; kk < 8; kk++) {
            uint32_t af[4];
            af[0] = *(const uint32_t*)(prow0 + kk * 32 + 4 * t);
            af[1] = *(const uint32_t*)(prow1 + kk * 32 + 4 * t);
            af[2] = *(const uint32_t*)(prow0 + kk * 32 + 4 * t + 16);
            af[3] = *(const uint32_t*)(prow1 + kk * 32 + 4 * t + 16);
#pragma unroll
            for (int j = 0; j < 8; j++) {
                int rb = (j * 8 + g) * VPIT + kk * 32 + 4 * t;
                uint32_t bf[2];
                bf[0] = *(const uint32_t*)(Vt + rb);
                bf[1] = *(const uint32_t*)(Vt + rb + 16);
                mma16(oa[j], af, bf);
            }
        }
        // next iteration's top __syncthreads covers buffer reuse
    }
#undef AFILL

    float i0 = 1.f / l0, i1 = 1.f / l1;
    int b = bh >> 4, h = bh & 15;
    int tr0 = b * SS + qt * 128 + band + g;
    __half* ob0 = out + (size_t)tr0 * DM + h * DH;
    __half* ob1 = out + (size_t)(tr0 + 8) * DM + h * DH;
#pragma unroll
    for (int j = 0; j < 8; j++) {
        int c = j * 8 + 2 * t;
        *(__half2*)(ob0 + c) = __floats2half2_rn(oa[j][0] * i0, oa[j][1] * i0);
        *(__half2*)(ob1 + c) = __floats2half2_rn(oa[j][2] * i1, oa[j][3] * i1);
    }
}

// ---------------- launcher ----------------
extern "C" void kernel_launch(void* const* d_in, const int* in_sizes, int n_in,
                              void* d_out, int out_size)
{
    const float* Q  = (const float*)d_in[0];
    const float* K  = (const float*)d_in[1];
    const float* V  = (const float*)d_in[2];
    const float* Wq = (const float*)d_in[3];
    const float* bq = (const float*)d_in[4];
    const float* Wk = (const float*)d_in[5];
    const float* bk = (const float*)d_in[6];
    const float* Wv = (const float*)d_in[7];
    const float* bv = (const float*)d_in[8];
    const float* Wo = (const float*)d_in[9];
    const float* bo = (const float*)d_in[10];

    __half *qh, *kh, *vth, *ah, *xh, *wh;
    cudaGetSymbolAddress((void**)&qh,  g_qh);
    cudaGetSymbolAddress((void**)&kh,  g_kh);
    cudaGetSymbolAddress((void**)&vth, g_vth);
    cudaGetSymbolAddress((void**)&ah,  g_ah);
    cudaGetSymbolAddress((void**)&xh,  g_xh);
    cudaGetSymbolAddress((void**)&wh,  g_wh);

    cudaFuncSetAttribute(attn_h, cudaFuncAttributeMaxDynamicSharedMemorySize, ASMEM);
    cudaFuncSetAttribute(gemm_h, cudaFuncAttributeMaxDynamicSharedMemorySize, GSMEM);

    // fp32 -> fp16 conversion (inputs + weights, one launch)
    const int total4 = 3 * N4I + 4 * N4W;   // 7,340,032
    cvt_all<<<total4 / 256, 256>>>(Q, K, V, Wq, Wk, Wv, Wo);

    // merged Q/K/V projection GEMMs
    GArgs gp;
    gp.A[0] = xh;               gp.A[1] = xh + (size_t)TOK * DM; gp.A[2] = xh + (size_t)2 * TOK * DM;
    gp.W[0] = wh;               gp.W[1] = wh + DM * DM;          gp.W[2] = wh + 2 * DM * DM;
    gp.bias[0] = bq;            gp.bias[1] = bk;                 gp.bias[2] = bv;
    gp.out[0] = qh;             gp.out[1] = kh;                  gp.out[2] = vth;
    gp.mode = 0;
    dim3 ggrid(DM / 128, TOK / 128, 3);   // (8, 64, 3)
    gemm_h<<<ggrid, 256, GSMEM>>>(gp);

    dim3 agrid(SS / 128, BB * NH);        // (16, 64)
    attn_h<<<agrid, 256, ASMEM>>>(qh, kh, vth, ah);

    // output projection (fp32 result)
    GArgs go;
    go.A[0] = ah;  go.A[1] = ah;  go.A[2] = ah;
    go.W[0] = wh + 3 * DM * DM; go.W[1] = go.W[0]; go.W[2] = go.W[0];
    go.bias[0] = bo; go.bias[1] = bo; go.bias[2] = bo;
    go.out[0] = d_out; go.out[1] = d_out; go.out[2] = d_out;
    go.mode = 1;
    dim3 ogrid(DM / 128, TOK / 128, 1);
    gemm_h<<<ogrid, 256, GSMEM>>>(go);
}

// round 12
// speedup vs baseline: 1.9232x; 1.0626x over previous
#include <cuda_runtime.h>
#include <cuda_fp16.h>
#include <cstdint>

// Problem constants
#define BB    4
#define SS    2048
#define DM    1024
#define NH    16
#define DH    64
#define TOK   (BB * SS)          // 8192 tokens

// ---------------- scratch (no cudaMalloc allowed) ----------------
__device__ __half g_qh[TOK * DM];      // [B,H,S,Dh]
__device__ __half g_kh[TOK * DM];      // [B,H,S,Dh]
__device__ __half g_vth[TOK * DM];     // [B,H,Dh,S]  (V transposed)
__device__ __half g_ah[TOK * DM];      // [B,S,D]     attn output
__device__ __half g_xh[3 * TOK * DM];  // fp16 inputs Q,K,V
__device__ __half g_wh[4 * DM * DM];   // fp16 weights Wq,Wk,Wv,Wo

// ---------------- helpers ----------------
__device__ __forceinline__ uint32_t smem_u32(const void* p) {
    uint32_t a;
    asm("{ .reg .u64 t; cvta.to.shared.u64 t, %1; cvt.u32.u64 %0, t; }" : "=r"(a) : "l"(p));
    return a;
}
__device__ __forceinline__ float ex2(float x) {
    float y;
    asm("ex2.approx.ftz.f32 %0, %1;" : "=f"(y) : "f"(x));
    return y;
}
__device__ __forceinline__ void cpasync16(uint32_t dst, const void* src) {
    asm volatile("cp.async.cg.shared.global [%0], [%1], 16;" :: "r"(dst), "l"(src));
}
#define CP_COMMIT()  asm volatile("cp.async.commit_group;" ::: "memory")
#define CP_WAIT(n)   asm volatile("cp.async.wait_group " #n ";" ::: "memory")

__device__ __forceinline__ void mma16(float* c, const uint32_t* a, const uint32_t* b) {
    asm volatile(
        "mma.sync.aligned.m16n8k16.row.col.f32.f16.f16.f32 "
        "{%0,%1,%2,%3},{%4,%5,%6,%7},{%8,%9},{%0,%1,%2,%3};\n"
        : "+f"(c[0]), "+f"(c[1]), "+f"(c[2]), "+f"(c[3])
        : "r"(a[0]), "r"(a[1]), "r"(a[2]), "r"(a[3]),
          "r"(b[0]), "r"(b[1]));
}
__device__ __forceinline__ uint32_t h2u(__half2 h) {
    return *reinterpret_cast<uint32_t*>(&h);
}
#define LDSM4(r0, r1, r2, r3, addr)                                            \
    asm volatile("ldmatrix.sync.aligned.m8n8.x4.shared.b16 {%0,%1,%2,%3}, [%4];" \
                 : "=r"(r0), "=r"(r1), "=r"(r2), "=r"(r3) : "r"(addr))

// ---------------- fp32 -> fp16 conversion pass ----------------
#define N4I (TOK * DM / 4)
#define N4W (DM * DM / 4)

__global__ void cvt_all(const float* __restrict__ Q, const float* __restrict__ K,
                        const float* __restrict__ V,
                        const float* __restrict__ Wq, const float* __restrict__ Wk,
                        const float* __restrict__ Wv, const float* __restrict__ Wo)
{
    int i = blockIdx.x * blockDim.x + threadIdx.x;
    const float4* s;
    __half2* d;
    int off;
    if (i < 3 * N4I) {
        int seg = i / N4I;
        off = i - seg * N4I;
        s = (const float4*)(seg == 0 ? Q : seg == 1 ? K : V);
        d = (__half2*)(g_xh + (size_t)seg * TOK * DM);
    } else {
        int j = i - 3 * N4I;
        int seg = j / N4W;
        off = j - seg * N4W;
        s = (const float4*)(seg == 0 ? Wq : seg == 1 ? Wk : seg == 2 ? Wv : Wo);
        d = (__half2*)(g_wh + (size_t)seg * DM * DM);
    }
    float4 v = s[off];
    d[2 * off]     = __floats2half2_rn(v.x, v.y);
    d[2 * off + 1] = __floats2half2_rn(v.z, v.w);
}

// ---------------- fp16 GEMM (mma m16n8k16 + ldmatrix, cp.async distance-2) ----------------
// C[8192,1024] = A[8192,1024(K-major)] @ W[1024,1024(K-major)]^T + bias
// smem rows: 32 halves, pitch 80B -> 20r mod 32 bank rotation: every ldmatrix
// 8-row phase covers all 32 banks (conflict-free).
#define GP    80
#define GSTG  (128 * GP * 2)     // 20480 per stage (A then B)
#define GSMEM (3 * GSTG)         // 61440

struct GArgs {
    const __half* A[3];
    const __half* W[3];
    const float*  bias[3];
    void*         out[3];
    int mode;
};

__global__ void __launch_bounds__(256, 2)
gemm_h(GArgs ga)
{
    extern __shared__ char smc[];
    const uint32_t sb = smem_u32(smc);
    const int z = blockIdx.z;
    const __half* __restrict__ A   = ga.A[z];
    const __half* __restrict__ W   = ga.W[z];
    const float* __restrict__ bias = ga.bias[z];
    const int mode = ga.mode;

    const int tid  = threadIdx.x;
    const int warp = tid >> 5, lane = tid & 31;
    const int g = lane >> 2, t = lane & 3;
    const int wm = warp >> 2, wn = warp & 3;
    const int bm = blockIdx.y * 128, bn = blockIdx.x * 128;
    const int lrow = lane & 7, sel = lane >> 3;

    // ldmatrix per-thread address offsets (A: a-frag order m0..m3; B: b-frag pairs)
    const uint32_t offA = (uint32_t)(lrow * GP + (sel & 1) * (8 * GP) + (sel >> 1) * 16);
    const uint32_t offB = (uint32_t)(lrow * GP + (sel & 1) * 16 + (sel >> 1) * (8 * GP));

    const __half* Ab = A + (size_t)bm * DM;
    const __half* Wb = W + (size_t)bn * DM;

    float acc[4][4][4];
#pragma unroll
    for (int i = 0; i < 4; i++)
#pragma unroll
        for (int j = 0; j < 4; j++)
#pragma unroll
            for (int e = 0; e < 4; e++) acc[i][j][e] = 0.f;

#define LOAD_TILE(kt, stg)                                                      \
    do {                                                                        \
        uint32_t bA = sb + (stg) * GSTG;                                        \
        uint32_t bB = bA + 128 * GP;                                            \
        int kc = (kt) * 32;                                                     \
        _Pragma("unroll")                                                       \
        for (int i_ = 0; i_ < 2; i_++) {                                        \
            int id = tid + i_ * 256;                                            \
            int r_ = id >> 2, c4 = id & 3;                                      \
            cpasync16(bA + r_ * GP + c4 * 16, Ab + (size_t)r_ * DM + kc + c4 * 8); \
            cpasync16(bB + r_ * GP + c4 * 16, Wb + (size_t)r_ * DM + kc + c4 * 8); \
        }                                                                       \
    } while (0)

    LOAD_TILE(0, 0); CP_COMMIT();
    LOAD_TILE(1, 1); CP_COMMIT();

    for (int tt = 0; tt < 32; tt++) {
        if (tt < 31) { CP_WAIT(1); } else { CP_WAIT(0); }
        __syncthreads();
        if (tt + 2 < 32) { LOAD_TILE(tt + 2, (tt + 2) % 3); CP_COMMIT(); }

        const uint32_t sAu = sb + (tt % 3) * GSTG;
        const uint32_t sBu = sAu + 128 * GP;
#pragma unroll
        for (int s = 0; s < 2; s++) {
            uint32_t af[4][4], bf[4][2];
#pragma unroll
            for (int i = 0; i < 4; i++)
                LDSM4(af[i][0], af[i][1], af[i][2], af[i][3],
                      sAu + (uint32_t)((wm * 64 + i * 16) * GP + s * 32) + offA);
#pragma unroll
            for (int j2 = 0; j2 < 2; j2++)
                LDSM4(bf[2 * j2][0], bf[2 * j2][1], bf[2 * j2 + 1][0], bf[2 * j2 + 1][1],
                      sBu + (uint32_t)((wn * 32 + j2 * 16) * GP + s * 32) + offB);
#pragma unroll
            for (int i = 0; i < 4; i++)
#pragma unroll
                for (int j = 0; j < 4; j++) mma16(acc[i][j], af[i], bf[j]);
        }
    }
#undef LOAD_TILE

    // epilogue
#pragma unroll
    for (int i = 0; i < 4; i++) {
#pragma unroll
        for (int j = 0; j < 4; j++) {
            int row0 = bm + wm * 64 + i * 16 + g;
            int col0 = bn + wn * 32 + j * 8 + 2 * t;
            float b0 = bias[col0], b1 = bias[col0 + 1];
            float c00 = acc[i][j][0] + b0, c01 = acc[i][j][1] + b1;
            float c10 = acc[i][j][2] + b0, c11 = acc[i][j][3] + b1;
            if (mode == 1) {
                float* out = (float*)ga.out[z];
                out[(size_t)row0 * DM + col0]           = c00;
                out[(size_t)row0 * DM + col0 + 1]       = c01;
                out[(size_t)(row0 + 8) * DM + col0]     = c10;
                out[(size_t)(row0 + 8) * DM + col0 + 1] = c11;
            } else {
                __half* out = (__half*)ga.out[z];
                int h = col0 >> 6, dh0 = col0 & 63;
                int b = row0 >> 11, s = row0 & 2047;
                if (z < 2) {
                    size_t base = (((size_t)(b * NH + h) * SS) + s) * DH + dh0;
                    *(__half2*)(out + base)          = __floats2half2_rn(c00, c01);
                    *(__half2*)(out + base + 8 * DH) = __floats2half2_rn(c10, c11);
                } else {
                    size_t base = ((size_t)(b * NH + h) * DH + dh0) * SS + s;
                    out[base]          = __float2half_rn(c00);
                    out[base + SS]     = __float2half_rn(c01);
                    out[base + 8]      = __float2half_rn(c10);
                    out[base + SS + 8] = __float2half_rn(c11);
                }
            }
        }
    }
}

// ---------------- Flash attention (fp16 mma m16n8k16 + ldmatrix) ----------------
// K smem [128 kv][64 dh] pitch 144B; V^T smem [64 dh][128 kv] pitch 272B;
// P smem [128 q][128 kv] fp16 pitch 272B. Pitches give 4r mod 32 bank rotation:
// ldmatrix phases cover all banks (conflict-free).
#define KPIT   144
#define VPIT   272
#define PPIT   272
#define KBYTES (128 * KPIT)          // 18432
#define VBYTES (64 * VPIT)           // 17408
#define BUFB   (KBYTES + VBYTES)     // 35840
#define POFF   (2 * BUFB)            // 71680
#define ASMEM  (POFF + 128 * PPIT)   // 106496

__global__ void __launch_bounds__(256, 1)
attn_h(const __half* __restrict__ q, const __half* __restrict__ k,
       const __half* __restrict__ vt, __half* __restrict__ out)
{
    extern __shared__ char smc[];
    const uint32_t sba = smem_u32(smc);

    const int tid = threadIdx.x, warp = tid >> 5, lane = tid & 31;
    const int g = lane >> 2, t = lane & 3;
    const int bh = blockIdx.y, qt = blockIdx.x;
    const int band = warp * 16;
    const int lrow = lane & 7, sel = lane >> 3;

    const uint32_t offK = (uint32_t)(lrow * KPIT + (sel & 1) * 16 + (sel >> 1) * (8 * KPIT));
    const uint32_t offV = (uint32_t)(lrow * VPIT + (sel & 1) * 16 + (sel >> 1) * (8 * VPIT));
    const uint32_t offP = (uint32_t)(lrow * PPIT + (sel & 1) * (8 * PPIT) + (sel >> 1) * 16);

    const __half* qb  = q  + (size_t)bh * SS * DH;
    const __half* kb  = k  + (size_t)bh * SS * DH;
    const __half* vtb = vt + (size_t)bh * DH * SS;

#define AFILL(tile, buf)                                                            \
    do {                                                                            \
        uint32_t kb_ = sba + (buf) * BUFB;                                          \
        uint32_t vb_ = kb_ + KBYTES;                                                \
        _Pragma("unroll")                                                           \
        for (int i_ = 0; i_ < 4; i_++) {                                            \
            int id = tid + i_ * 256;                                                \
            int rk = id >> 3, ck = id & 7;                                          \
            cpasync16(kb_ + rk * KPIT + ck * 16,                                    \
                      kb + (size_t)((tile) * 128 + rk) * DH + ck * 8);              \
            int rv = id >> 4, cv = id & 15;                                         \
            cpasync16(vb_ + rv * VPIT + cv * 16,                                    \
                      vtb + (size_t)rv * SS + (tile) * 128 + cv * 8);               \
        }                                                                           \
    } while (0)

    AFILL(0, 0); CP_COMMIT();

    // Q fragments (4 k16-steps over Dh=64)
    uint32_t qf[4][4];
    {
        int r0 = qt * 128 + band + g;
        const __half* q0 = qb + (size_t)r0 * DH;
        const __half* q1 = q0 + 8 * DH;
#pragma unroll
        for (int s = 0; s < 4; s++) {
            qf[s][0] = *(const uint32_t*)(q0 + s * 16 + 2 * t);
            qf[s][1] = *(const uint32_t*)(q1 + s * 16 + 2 * t);
            qf[s][2] = *(const uint32_t*)(q0 + s * 16 + 2 * t + 8);
            qf[s][3] = *(const uint32_t*)(q1 + s * 16 + 2 * t + 8);
        }
    }

    const float SCL = 0.125f * 1.4426950408889634f;  // 1/sqrt(64) * log2(e)

    float m0 = -INFINITY, m1 = -INFINITY, l0 = 0.f, l1 = 0.f;
    float oa[8][4];
#pragma unroll
    for (int j = 0; j < 8; j++)
#pragma unroll
        for (int e = 0; e < 4; e++) oa[j][e] = 0.f;

    char* prow0 = smc + POFF + (band + g) * PPIT;
    char* prow1 = prow0 + 8 * PPIT;
    const uint32_t pbase = sba + POFF + (uint32_t)(band * PPIT);

    for (int kv = 0; kv < 16; kv++) {
        CP_WAIT(0);
        __syncthreads();
        if (kv < 15) { AFILL(kv + 1, (kv + 1) & 1); CP_COMMIT(); }

        const uint32_t Ksu = sba + (kv & 1) * BUFB;
        const uint32_t Vtu = Ksu + KBYTES;

        // S = Q * K^T  (ldmatrix b-frag pairs)
        float sf[16][4];
#pragma unroll
        for (int j = 0; j < 16; j++)
#pragma unroll
            for (int e = 0; e < 4; e++) sf[j][e] = 0.f;
#pragma unroll
        for (int s = 0; s < 4; s++) {
#pragma unroll
            for (int j2 = 0; j2 < 8; j2++) {
                uint32_t b0[2], b1[2];
                LDSM4(b0[0], b0[1], b1[0], b1[1],
                      Ksu + (uint32_t)(j2 * 16 * KPIT + s * 32) + offK);
                mma16(sf[2 * j2],     qf[s], b0);
                mma16(sf[2 * j2 + 1], qf[s], b1);
            }
        }
        // softmax scale (log2 domain)
#pragma unroll
        for (int j = 0; j < 16; j++)
#pragma unroll
            for (int e = 0; e < 4; e++) sf[j][e] *= SCL;

        // online softmax
        float mt0 = -INFINITY, mt1 = -INFINITY;
#pragma unroll
        for (int j = 0; j < 16; j++) {
            mt0 = fmaxf(mt0, fmaxf(sf[j][0], sf[j][1]));
            mt1 = fmaxf(mt1, fmaxf(sf[j][2], sf[j][3]));
        }
        mt0 = fmaxf(mt0, __shfl_xor_sync(0xffffffffu, mt0, 1));
        mt0 = fmaxf(mt0, __shfl_xor_sync(0xffffffffu, mt0, 2));
        mt1 = fmaxf(mt1, __shfl_xor_sync(0xffffffffu, mt1, 1));
        mt1 = fmaxf(mt1, __shfl_xor_sync(0xffffffffu, mt1, 2));

        float mn0 = fmaxf(m0, mt0), mn1 = fmaxf(m1, mt1);
        float al0 = ex2(m0 - mn0), al1 = ex2(m1 - mn1);

        float rs0 = 0.f, rs1 = 0.f;
#pragma unroll
        for (int j = 0; j < 16; j++) {
            float p0 = ex2(sf[j][0] - mn0);
            float p1 = ex2(sf[j][1] - mn0);
            float p2 = ex2(sf[j][2] - mn1);
            float p3 = ex2(sf[j][3] - mn1);
            rs0 += p0 + p1;
            rs1 += p2 + p3;
            *(uint32_t*)(prow0 + 16 * j + 4 * t) = h2u(__floats2half2_rn(p0, p1));
            *(uint32_t*)(prow1 + 16 * j + 4 * t) = h2u(__floats2half2_rn(p2, p3));
        }
        rs0 += __shfl_xor_sync(0xffffffffu, rs0, 1);
        rs0 += __shfl_xor_sync(0xffffffffu, rs0, 2);
        rs1 += __shfl_xor_sync(0xffffffffu, rs1, 1);
        rs1 += __shfl_xor_sync(0xffffffffu, rs1, 2);

        l0 = l0 * al0 + rs0;
        l1 = l1 * al1 + rs1;
        m0 = mn0;
        m1 = mn1;
#pragma unroll
        for (int j = 0; j < 8; j++) {
            oa[j][0] *= al0; oa[j][1] *= al0;
            oa[j][2] *= al1; oa[j][3] *= al1;
        }
        __syncwarp();   // P rows warp-private: order STS before ldmatrix

        // O += P * V   (ldmatrix for P a-frags and V b-frag pairs)
#pragma unroll
        for (int kk = 0; kk < 8; kk++) {
            uint32_t af[4];
            LDSM4(af[0], af[1], af[2], af[3],
                  pbase + (uint32_t)(kk * 32) + offP);
#pragma unroll
            for (int j2 = 0; j2 < 4; j2++) {
                uint32_t b0[2], b1[2];
                LDSM4(b0[0], b0[1], b1[0], b1[1],
                      Vtu + (uint32_t)(j2 * 16 * VPIT + kk * 32) + offV);
                mma16(oa[2 * j2],     af, b0);
                mma16(oa[2 * j2 + 1], af, b1);
            }
        }
        // next iteration's top __syncthreads covers buffer reuse
    }
#undef AFILL

    float i0 = 1.f / l0, i1 = 1.f / l1;
    int b = bh >> 4, h = bh & 15;
    int tr0 = b * SS + qt * 128 + band + g;
    __half* ob0 = out + (size_t)tr0 * DM + h * DH;
    __half* ob1 = out + (size_t)(tr0 + 8) * DM + h * DH;
#pragma unroll
    for (int j = 0; j < 8; j++) {
        int c = j * 8 + 2 * t;
        *(__half2*)(ob0 + c) = __floats2half2_rn(oa[j][0] * i0, oa[j][1] * i0);
        *(__half2*)(ob1 + c) = __floats2half2_rn(oa[j][2] * i1, oa[j][3] * i1);
    }
}

// ---------------- launcher ----------------
extern "C" void kernel_launch(void* const* d_in, const int* in_sizes, int n_in,
                              void* d_out, int out_size)
{
    const float* Q  = (const float*)d_in[0];
    const float* K  = (const float*)d_in[1];
    const float* V  = (const float*)d_in[2];
    const float* Wq = (const float*)d_in[3];
    const float* bq = (const float*)d_in[4];
    const float* Wk = (const float*)d_in[5];
    const float* bk = (const float*)d_in[6];
    const float* Wv = (const float*)d_in[7];
    const float* bv = (const float*)d_in[8];
    const float* Wo = (const float*)d_in[9];
    const float* bo = (const float*)d_in[10];

    __half *qh, *kh, *vth, *ah, *xh, *wh;
    cudaGetSymbolAddress((void**)&qh,  g_qh);
    cudaGetSymbolAddress((void**)&kh,  g_kh);
    cudaGetSymbolAddress((void**)&vth, g_vth);
    cudaGetSymbolAddress((void**)&ah,  g_ah);
    cudaGetSymbolAddress((void**)&xh,  g_xh);
    cudaGetSymbolAddress((void**)&wh,  g_wh);

    cudaFuncSetAttribute(attn_h, cudaFuncAttributeMaxDynamicSharedMemorySize, ASMEM);
    cudaFuncSetAttribute(gemm_h, cudaFuncAttributeMaxDynamicSharedMemorySize, GSMEM);

    // fp32 -> fp16 conversion (inputs + weights, one launch)
    const int total4 = 3 * N4I + 4 * N4W;
    cvt_all<<<total4 / 256, 256>>>(Q, K, V, Wq, Wk, Wv, Wo);

    // merged Q/K/V projection GEMMs
    GArgs gp;
    gp.A[0] = xh;    gp.A[1] = xh + (size_t)TOK * DM; gp.A[2] = xh + (size_t)2 * TOK * DM;
    gp.W[0] = wh;    gp.W[1] = wh + DM * DM;          gp.W[2] = wh + 2 * DM * DM;
    gp.bias[0] = bq; gp.bias[1] = bk;                 gp.bias[2] = bv;
    gp.out[0] = qh;  gp.out[1] = kh;                  gp.out[2] = vth;
    gp.mode = 0;
    dim3 ggrid(DM / 128, TOK / 128, 3);   // (8, 64, 3)
    gemm_h<<<ggrid, 256, GSMEM>>>(gp);

    dim3 agrid(SS / 128, BB * NH);        // (16, 64)
    attn_h<<<agrid, 256, ASMEM>>>(qh, kh, vth, ah);

    // output projection (fp32 result)
    GArgs go;
    go.A[0] = ah;  go.A[1] = ah;  go.A[2] = ah;
    go.W[0] = wh + 3 * DM * DM; go.W[1] = go.W[0]; go.W[2] = go.W[0];
    go.bias[0] = bo; go.bias[1] = bo; go.bias[2] = bo;
    go.out[0] = d_out; go.out[1] = d_out; go.out[2] = d_out;
    go.mode = 1;
    dim3 ogrid(DM / 128, TOK / 128, 1);
    gemm_h<<<ogrid, 256, GSMEM>>>(go);
}

// round 13
// speedup vs baseline: 2.0570x; 1.0696x over previous
#include <cuda_runtime.h>
#include <cuda_fp16.h>
#include <cstdint>

// Problem constants
#define BB    4
#define SS    2048
#define DM    1024
#define NH    16
#define DH    64
#define TOK   (BB * SS)          // 8192 tokens

// ---------------- scratch (no cudaMalloc allowed) ----------------
__device__ __half g_qh[TOK * DM];      // [B,H,S,Dh]
__device__ __half g_kh[TOK * DM];      // [B,H,S,Dh]
__device__ __half g_vth[TOK * DM];     // [B,H,Dh,S]  (V transposed)
__device__ __half g_ah[TOK * DM];      // [B,S,D]     attn output
__device__ __half g_wh[4 * DM * DM];   // fp16 weights Wq,Wk,Wv,Wo

// ---------------- helpers ----------------
__device__ __forceinline__ uint32_t smem_u32(const void* p) {
    uint32_t a;
    asm("{ .reg .u64 t; cvta.to.shared.u64 t, %1; cvt.u32.u64 %0, t; }" : "=r"(a) : "l"(p));
    return a;
}
__device__ __forceinline__ float ex2(float x) {
    float y;
    asm("ex2.approx.ftz.f32 %0, %1;" : "=f"(y) : "f"(x));
    return y;
}
__device__ __forceinline__ void cpasync16(uint32_t dst, const void* src) {
    asm volatile("cp.async.cg.shared.global [%0], [%1], 16;" :: "r"(dst), "l"(src));
}
#define CP_COMMIT()  asm volatile("cp.async.commit_group;" ::: "memory")
#define CP_WAIT(n)   asm volatile("cp.async.wait_group " #n ";" ::: "memory")

__device__ __forceinline__ void mma16(float* c, const uint32_t* a, const uint32_t* b) {
    asm volatile(
        "mma.sync.aligned.m16n8k16.row.col.f32.f16.f16.f32 "
        "{%0,%1,%2,%3},{%4,%5,%6,%7},{%8,%9},{%0,%1,%2,%3};\n"
        : "+f"(c[0]), "+f"(c[1]), "+f"(c[2]), "+f"(c[3])
        : "r"(a[0]), "r"(a[1]), "r"(a[2]), "r"(a[3]),
          "r"(b[0]), "r"(b[1]));
}
__device__ __forceinline__ uint32_t h2u(__half2 h) {
    return *reinterpret_cast<uint32_t*>(&h);
}
#define LDSM4(r0, r1, r2, r3, addr)                                            \
    asm volatile("ldmatrix.sync.aligned.m8n8.x4.shared.b16 {%0,%1,%2,%3}, [%4];" \
                 : "=r"(r0), "=r"(r1), "=r"(r2), "=r"(r3) : "r"(addr))
#define STS64(addr, lo, hi) \
    asm volatile("st.shared.v2.b32 [%0], {%1,%2};" :: "r"(addr), "r"(lo), "r"(hi))

// ---------------- fp32 -> fp16 weight conversion (inputs converted in-GEMM) ----
#define N4W (DM * DM / 4)

__global__ void cvt_w(const float* __restrict__ Wq, const float* __restrict__ Wk,
                      const float* __restrict__ Wv, const float* __restrict__ Wo)
{
    int i = blockIdx.x * blockDim.x + threadIdx.x;
    int seg = i / N4W;
    int off = i - seg * N4W;
    const float4* s = (const float4*)(seg == 0 ? Wq : seg == 1 ? Wk : seg == 2 ? Wv : Wo);
    __half2* d = (__half2*)(g_wh + (size_t)seg * DM * DM);
    float4 v = s[off];
    d[2 * off]     = __floats2half2_rn(v.x, v.y);
    d[2 * off + 1] = __floats2half2_rn(v.z, v.w);
}

// ---------------- fp16 GEMM (mma m16n8k16 + ldmatrix, cp.async distance-2) ----------------
// C[8192,1024] = A[8192,1024(K-major)] @ W[1024,1024(K-major)]^T + bias
// CVTA=true: A read as raw fp32, converted to fp16 in-register (LDG prefetch at
// iter top, cvt+STS after compute). CVTA=false: fp16 A via cp.async.
// pitch 80B rows -> 20r mod 32 bank rotation: ldmatrix conflict-free.
#define GP    80
#define GSTG  (128 * GP * 2)     // 20480 per stage (A then B)
#define GSMEM (3 * GSTG)         // 61440

struct GArgs {
    const float*  Af[3];   // fp32 A (CVTA=true)
    const __half* A[3];    // fp16 A (CVTA=false)
    const __half* W[3];
    const float*  bias[3];
    void*         out[3];
    int mode;
};

template <bool CVTA>
__global__ void __launch_bounds__(256, 2)
gemm_h(GArgs ga)
{
    extern __shared__ char smc[];
    const uint32_t sb = smem_u32(smc);
    const int z = blockIdx.z;
    const float* __restrict__ Af   = ga.Af[z];
    const __half* __restrict__ A   = ga.A[z];
    const __half* __restrict__ W   = ga.W[z];
    const float* __restrict__ bias = ga.bias[z];
    const int mode = ga.mode;

    const int tid  = threadIdx.x;
    const int warp = tid >> 5, lane = tid & 31;
    const int g = lane >> 2, t = lane & 3;
    const int wm = warp >> 2, wn = warp & 3;
    const int bm = blockIdx.y * 128, bn = blockIdx.x * 128;
    const int lrow = lane & 7, sel = lane >> 3;

    const uint32_t offA = (uint32_t)(lrow * GP + (sel & 1) * (8 * GP) + (sel >> 1) * 16);
    const uint32_t offB = (uint32_t)(lrow * GP + (sel & 1) * 16 + (sel >> 1) * (8 * GP));

    const float*  Ab32 = Af + (size_t)bm * DM;
    const __half* Ab   = A + (size_t)bm * DM;
    const __half* Wb   = W + (size_t)bn * DM;

    float acc[4][4][4];
#pragma unroll
    for (int i = 0; i < 4; i++)
#pragma unroll
        for (int j = 0; j < 4; j++)
#pragma unroll
            for (int e = 0; e < 4; e++) acc[i][j][e] = 0.f;

    // B tile: 128 rows x 32 halves, 2 cp.async per thread
#define LOAD_B(kt, stg)                                                         \
    do {                                                                        \
        uint32_t bB = sb + (stg) * GSTG + 128 * GP;                             \
        int kc = (kt) * 32;                                                     \
        _Pragma("unroll")                                                       \
        for (int i_ = 0; i_ < 2; i_++) {                                        \
            int id = tid + i_ * 256;                                            \
            int r_ = id >> 2, c4 = id & 3;                                      \
            cpasync16(bB + r_ * GP + c4 * 16, Wb + (size_t)r_ * DM + kc + c4 * 8); \
        }                                                                       \
    } while (0)

#define LOAD_A16(kt, stg)                                                       \
    do {                                                                        \
        uint32_t bA = sb + (stg) * GSTG;                                        \
        int kc = (kt) * 32;                                                     \
        _Pragma("unroll")                                                       \
        for (int i_ = 0; i_ < 2; i_++) {                                        \
            int id = tid + i_ * 256;                                            \
            int r_ = id >> 2, c4 = id & 3;                                      \
            cpasync16(bA + r_ * GP + c4 * 16, Ab + (size_t)r_ * DM + kc + c4 * 8); \
        }                                                                       \
    } while (0)

    // prologue
    if (CVTA) {
        // A tiles 0,1: fp32 LDG -> cvt -> STS (one-time latency)
#pragma unroll
        for (int pt = 0; pt < 2; pt++) {
            uint32_t bA = sb + pt * GSTG;
#pragma unroll
            for (int i_ = 0; i_ < 4; i_++) {
                int fi = tid + i_ * 256;          // 0..1023 float4
                int r_ = fi >> 3, c4 = fi & 7;
                float4 f = *(const float4*)(Ab32 + (size_t)r_ * DM + pt * 32 + c4 * 4);
                STS64(bA + r_ * GP + c4 * 8,
                      h2u(__floats2half2_rn(f.x, f.y)),
                      h2u(__floats2half2_rn(f.z, f.w)));
            }
        }
        LOAD_B(0, 0); CP_COMMIT();
        LOAD_B(1, 1); CP_COMMIT();
    } else {
        LOAD_A16(0, 0); LOAD_B(0, 0); CP_COMMIT();
        LOAD_A16(1, 1); LOAD_B(1, 1); CP_COMMIT();
    }

    for (int tt = 0; tt < 32; tt++) {
        if (tt < 31) { CP_WAIT(1); } else { CP_WAIT(0); }
        __syncthreads();

        const bool pref = (tt + 2 < 32);
        float4 pre[4];
        if (pref) {
            const int stg2 = (tt + 2) % 3;
            if (CVTA) {
                // issue fp32 LDGs now; convert+store after the compute block
                int kc = (tt + 2) * 32;
#pragma unroll
                for (int i_ = 0; i_ < 4; i_++) {
                    int fi = tid + i_ * 256;
                    int r_ = fi >> 3, c4 = fi & 7;
                    pre[i_] = *(const float4*)(Ab32 + (size_t)r_ * DM + kc + c4 * 4);
                }
                LOAD_B(tt + 2, stg2);
            } else {
                LOAD_A16(tt + 2, stg2);
                LOAD_B(tt + 2, stg2);
            }
        }

        const uint32_t sAu = sb + (tt % 3) * GSTG;
        const uint32_t sBu = sAu + 128 * GP;
#pragma unroll
        for (int s = 0; s < 2; s++) {
            uint32_t af[4][4], bf[4][2];
#pragma unroll
            for (int i = 0; i < 4; i++)
                LDSM4(af[i][0], af[i][1], af[i][2], af[i][3],
                      sAu + (uint32_t)((wm * 64 + i * 16) * GP + s * 32) + offA);
#pragma unroll
            for (int j2 = 0; j2 < 2; j2++)
                LDSM4(bf[2 * j2][0], bf[2 * j2][1], bf[2 * j2 + 1][0], bf[2 * j2 + 1][1],
                      sBu + (uint32_t)((wn * 32 + j2 * 16) * GP + s * 32) + offB);
#pragma unroll
            for (int i = 0; i < 4; i++)
#pragma unroll
                for (int j = 0; j < 4; j++) mma16(acc[i][j], af[i], bf[j]);
        }

        if (CVTA && pref) {
            uint32_t bA = sb + ((tt + 2) % 3) * GSTG;
#pragma unroll
            for (int i_ = 0; i_ < 4; i_++) {
                int fi = tid + i_ * 256;
                int r_ = fi >> 3, c4 = fi & 7;
                STS64(bA + r_ * GP + c4 * 8,
                      h2u(__floats2half2_rn(pre[i_].x, pre[i_].y)),
                      h2u(__floats2half2_rn(pre[i_].z, pre[i_].w)));
            }
        }
        if (pref) CP_COMMIT();
    }
#undef LOAD_B
#undef LOAD_A16

    // epilogue
#pragma unroll
    for (int i = 0; i < 4; i++) {
#pragma unroll
        for (int j = 0; j < 4; j++) {
            int row0 = bm + wm * 64 + i * 16 + g;
            int col0 = bn + wn * 32 + j * 8 + 2 * t;
            float b0 = bias[col0], b1 = bias[col0 + 1];
            float c00 = acc[i][j][0] + b0, c01 = acc[i][j][1] + b1;
            float c10 = acc[i][j][2] + b0, c11 = acc[i][j][3] + b1;
            if (mode == 1) {
                float* out = (float*)ga.out[z];
                out[(size_t)row0 * DM + col0]           = c00;
                out[(size_t)row0 * DM + col0 + 1]       = c01;
                out[(size_t)(row0 + 8) * DM + col0]     = c10;
                out[(size_t)(row0 + 8) * DM + col0 + 1] = c11;
            } else {
                __half* out = (__half*)ga.out[z];
                int h = col0 >> 6, dh0 = col0 & 63;
                int b = row0 >> 11, s = row0 & 2047;
                if (z < 2) {
                    size_t base = (((size_t)(b * NH + h) * SS) + s) * DH + dh0;
                    *(__half2*)(out + base)          = __floats2half2_rn(c00, c01);
                    *(__half2*)(out + base + 8 * DH) = __floats2half2_rn(c10, c11);
                } else {
                    size_t base = ((size_t)(b * NH + h) * DH + dh0) * SS + s;
                    out[base]          = __float2half_rn(c00);
                    out[base + SS]     = __float2half_rn(c01);
                    out[base + 8]      = __float2half_rn(c10);
                    out[base + SS + 8] = __float2half_rn(c11);
                }
            }
        }
    }
}

// ---------------- Flash attention (fp16 mma + ldmatrix, register-resident P) --------
// S C-fragment layout == PV A-fragment layout -> P never touches smem.
// K smem [128 kv][64 dh] pitch 144B; V^T smem [64 dh][128 kv] pitch 272B.
#define KPIT   144
#define VPIT   272
#define KBYTES (128 * KPIT)          // 18432
#define VBYTES (64 * VPIT)           // 17408
#define BUFB   (KBYTES + VBYTES)     // 35840
#define ASMEM  (2 * BUFB)            // 71680

__global__ void __launch_bounds__(256, 1)
attn_h(const __half* __restrict__ q, const __half* __restrict__ k,
       const __half* __restrict__ vt, __half* __restrict__ out)
{
    extern __shared__ char smc[];
    const uint32_t sba = smem_u32(smc);

    const int tid = threadIdx.x, warp = tid >> 5, lane = tid & 31;
    const int g = lane >> 2, t = lane & 3;
    const int bh = blockIdx.y, qt = blockIdx.x;
    const int band = warp * 16;
    const int lrow = lane & 7, sel = lane >> 3;

    const uint32_t offK = (uint32_t)(lrow * KPIT + (sel & 1) * 16 + (sel >> 1) * (8 * KPIT));
    const uint32_t offV = (uint32_t)(lrow * VPIT + (sel & 1) * 16 + (sel >> 1) * (8 * VPIT));

    const __half* qb  = q  + (size_t)bh * SS * DH;
    const __half* kb  = k  + (size_t)bh * SS * DH;
    const __half* vtb = vt + (size_t)bh * DH * SS;

#define AFILL(tile, buf)                                                            \
    do {                                                                            \
        uint32_t kb_ = sba + (buf) * BUFB;                                          \
        uint32_t vb_ = kb_ + KBYTES;                                                \
        _Pragma("unroll")                                                           \
        for (int i_ = 0; i_ < 4; i_++) {                                            \
            int id = tid + i_ * 256;                                                \
            int rk = id >> 3, ck = id & 7;                                          \
            cpasync16(kb_ + rk * KPIT + ck * 16,                                    \
                      kb + (size_t)((tile) * 128 + rk) * DH + ck * 8);              \
            int rv = id >> 4, cv = id & 15;                                         \
            cpasync16(vb_ + rv * VPIT + cv * 16,                                    \
                      vtb + (size_t)rv * SS + (tile) * 128 + cv * 8);               \
        }                                                                           \
    } while (0)

    AFILL(0, 0); CP_COMMIT();

    // Q fragments with softmax scale folded in (fp16 multiply)
    const float SCL = 0.125f * 1.4426950408889634f;  // 1/sqrt(64) * log2(e)
    const __half2 sclh = __float2half2_rn(SCL);
    uint32_t qf[4][4];
    {
        int r0 = qt * 128 + band + g;
        const __half* q0 = qb + (size_t)r0 * DH;
        const __half* q1 = q0 + 8 * DH;
#pragma unroll
        for (int s = 0; s < 4; s++) {
            qf[s][0] = h2u(__hmul2(*(const __half2*)(q0 + s * 16 + 2 * t), sclh));
            qf[s][1] = h2u(__hmul2(*(const __half2*)(q1 + s * 16 + 2 * t), sclh));
            qf[s][2] = h2u(__hmul2(*(const __half2*)(q0 + s * 16 + 2 * t + 8), sclh));
            qf[s][3] = h2u(__hmul2(*(const __half2*)(q1 + s * 16 + 2 * t + 8), sclh));
        }
    }

    float m0 = -INFINITY, m1 = -INFINITY, l0 = 0.f, l1 = 0.f;
    float oa[8][4];
#pragma unroll
    for (int j = 0; j < 8; j++)
#pragma unroll
        for (int e = 0; e < 4; e++) oa[j][e] = 0.f;

    for (int kv = 0; kv < 16; kv++) {
        CP_WAIT(0);
        __syncthreads();
        if (kv < 15) { AFILL(kv + 1, (kv + 1) & 1); CP_COMMIT(); }

        const uint32_t Ksu = sba + (kv & 1) * BUFB;
        const uint32_t Vtu = Ksu + KBYTES;

        // S = Q * K^T  (logits in log2 domain; scale pre-folded into Q)
        float sf[16][4];
#pragma unroll
        for (int j = 0; j < 16; j++)
#pragma unroll
            for (int e = 0; e < 4; e++) sf[j][e] = 0.f;
#pragma unroll
        for (int s = 0; s < 4; s++) {
#pragma unroll
            for (int j2 = 0; j2 < 8; j2++) {
                uint32_t b0[2], b1[2];
                LDSM4(b0[0], b0[1], b1[0], b1[1],
                      Ksu + (uint32_t)(j2 * 16 * KPIT + s * 32) + offK);
                mma16(sf[2 * j2],     qf[s], b0);
                mma16(sf[2 * j2 + 1], qf[s], b1);
            }
        }

        // online softmax
        float mt0 = -INFINITY, mt1 = -INFINITY;
#pragma unroll
        for (int j = 0; j < 16; j++) {
            mt0 = fmaxf(mt0, fmaxf(sf[j][0], sf[j][1]));
            mt1 = fmaxf(mt1, fmaxf(sf[j][2], sf[j][3]));
        }
        mt0 = fmaxf(mt0, __shfl_xor_sync(0xffffffffu, mt0, 1));
        mt0 = fmaxf(mt0, __shfl_xor_sync(0xffffffffu, mt0, 2));
        mt1 = fmaxf(mt1, __shfl_xor_sync(0xffffffffu, mt1, 1));
        mt1 = fmaxf(mt1, __shfl_xor_sync(0xffffffffu, mt1, 2));

        float mn0 = fmaxf(m0, mt0), mn1 = fmaxf(m1, mt1);
        float al0 = ex2(m0 - mn0), al1 = ex2(m1 - mn1);

        // P stays in registers: C-frag(S) layout == A-frag(PV) layout
        uint32_t pf[16][2];
        float rs0 = 0.f, rs1 = 0.f;
#pragma unroll
        for (int j = 0; j < 16; j++) {
            float p0 = ex2(sf[j][0] - mn0);
            float p1 = ex2(sf[j][1] - mn0);
            float p2 = ex2(sf[j][2] - mn1);
            float p3 = ex2(sf[j][3] - mn1);
            rs0 += p0 + p1;
            rs1 += p2 + p3;
            pf[j][0] = h2u(__floats2half2_rn(p0, p1));   // row g
            pf[j][1] = h2u(__floats2half2_rn(p2, p3));   // row g+8
        }
        rs0 += __shfl_xor_sync(0xffffffffu, rs0, 1);
        rs0 += __shfl_xor_sync(0xffffffffu, rs0, 2);
        rs1 += __shfl_xor_sync(0xffffffffu, rs1, 1);
        rs1 += __shfl_xor_sync(0xffffffffu, rs1, 2);

        l0 = l0 * al0 + rs0;
        l1 = l1 * al1 + rs1;
        m0 = mn0;
        m1 = mn1;
#pragma unroll
        for (int j = 0; j < 8; j++) {
            oa[j][0] *= al0; oa[j][1] *= al0;
            oa[j][2] *= al1; oa[j][3] *= al1;
        }

        // O += P * V  (P from registers, V via ldmatrix)
#pragma unroll
        for (int kk = 0; kk < 8; kk++) {
            uint32_t af[4];
            af[0] = pf[2 * kk][0];
            af[1] = pf[2 * kk][1];
            af[2] = pf[2 * kk + 1][0];
            af[3] = pf[2 * kk + 1][1];
#pragma unroll
            for (int j2 = 0; j2 < 4; j2++) {
                uint32_t b0[2], b1[2];
                LDSM4(b0[0], b0[1], b1[0], b1[1],
                      Vtu + (uint32_t)(j2 * 16 * VPIT + kk * 32) + offV);
                mma16(oa[2 * j2],     af, b0);
                mma16(oa[2 * j2 + 1], af, b1);
            }
        }
        // next iteration's top __syncthreads covers buffer reuse
    }
#undef AFILL

    float i0 = 1.f / l0, i1 = 1.f / l1;
    int b = bh >> 4, h = bh & 15;
    int tr0 = b * SS + qt * 128 + band + g;
    __half* ob0 = out + (size_t)tr0 * DM + h * DH;
    __half* ob1 = out + (size_t)(tr0 + 8) * DM + h * DH;
#pragma unroll
    for (int j = 0; j < 8; j++) {
        int c = j * 8 + 2 * t;
        *(__half2*)(ob0 + c) = __floats2half2_rn(oa[j][0] * i0, oa[j][1] * i0);
        *(__half2*)(ob1 + c) = __floats2half2_rn(oa[j][2] * i1, oa[j][3] * i1);
    }
}

// ---------------- launcher ----------------
extern "C" void kernel_launch(void* const* d_in, const int* in_sizes, int n_in,
                              void* d_out, int out_size)
{
    const float* Q  = (const float*)d_in[0];
    const float* K  = (const float*)d_in[1];
    const float* V  = (const float*)d_in[2];
    const float* Wq = (const float*)d_in[3];
    const float* bq = (const float*)d_in[4];
    const float* Wk = (const float*)d_in[5];
    const float* bk = (const float*)d_in[6];
    const float* Wv = (const float*)d_in[7];
    const float* bv = (const float*)d_in[8];
    const float* Wo = (const float*)d_in[9];
    const float* bo = (const float*)d_in[10];

    __half *qh, *kh, *vth, *ah, *wh;
    cudaGetSymbolAddress((void**)&qh,  g_qh);
    cudaGetSymbolAddress((void**)&kh,  g_kh);
    cudaGetSymbolAddress((void**)&vth, g_vth);
    cudaGetSymbolAddress((void**)&ah,  g_ah);
    cudaGetSymbolAddress((void**)&wh,  g_wh);

    cudaFuncSetAttribute(attn_h, cudaFuncAttributeMaxDynamicSharedMemorySize, ASMEM);
    cudaFuncSetAttribute(gemm_h<true>,  cudaFuncAttributeMaxDynamicSharedMemorySize, GSMEM);
    cudaFuncSetAttribute(gemm_h<false>, cudaFuncAttributeMaxDynamicSharedMemorySize, GSMEM);

    // fp32 -> fp16 weights only (inputs converted inside the QKV GEMM)
    cvt_w<<<4 * N4W / 256, 256>>>(Wq, Wk, Wv, Wo);

    // merged Q/K/V projection GEMMs: raw fp32 A, in-kernel conversion
    GArgs gp;
    gp.Af[0] = Q;    gp.Af[1] = K;    gp.Af[2] = V;
    gp.A[0] = nullptr; gp.A[1] = nullptr; gp.A[2] = nullptr;
    gp.W[0] = wh;    gp.W[1] = wh + DM * DM; gp.W[2] = wh + 2 * DM * DM;
    gp.bias[0] = bq; gp.bias[1] = bk;        gp.bias[2] = bv;
    gp.out[0] = qh;  gp.out[1] = kh;         gp.out[2] = vth;
    gp.mode = 0;
    dim3 ggrid(DM / 128, TOK / 128, 3);   // (8, 64, 3)
    gemm_h<true><<<ggrid, 256, GSMEM>>>(gp);

    dim3 agrid(SS / 128, BB * NH);        // (16, 64)
    attn_h<<<agrid, 256, ASMEM>>>(qh, kh, vth, ah);

    // output projection (fp16 A from attn, fp32 result)
    GArgs go;
    go.Af[0] = nullptr; go.Af[1] = nullptr; go.Af[2] = nullptr;
    go.A[0] = ah;  go.A[1] = ah;  go.A[2] = ah;
    go.W[0] = wh + 3 * DM * DM; go.W[1] = go.W[0]; go.W[2] = go.W[0];
    go.bias[0] = bo; go.bias[1] = bo; go.bias[2] = bo;
    go.out[0] = d_out; go.out[1] = d_out; go.out[2] = d_out;
    go.mode = 1;
    dim3 ogrid(DM / 128, TOK / 128, 1);
    gemm_h<false><<<ogrid, 256, GSMEM>>>(go);
}

// round 14
// speedup vs baseline: 2.0843x; 1.0133x over previous
#include <cuda_runtime.h>
#include <cuda_fp16.h>
#include <cstdint>

// Problem constants
#define BB    4
#define SS    2048
#define DM    1024
#define NH    16
#define DH    64
#define TOK   (BB * SS)          // 8192 tokens

// ---------------- scratch (no cudaMalloc allowed) ----------------
__device__ __half g_qh[TOK * DM];      // [B,H,S,Dh]
__device__ __half g_kh[TOK * DM];      // [B,H,S,Dh]
__device__ __half g_vth[TOK * DM];     // [B,H,Dh,S]  (V transposed)
__device__ __half g_ah[TOK * DM];      // [B,S,D]     attn output
__device__ __half g_wh[4 * DM * DM];   // fp16 weights Wq,Wk,Wv,Wo

// ---------------- helpers ----------------
__device__ __forceinline__ uint32_t smem_u32(const void* p) {
    uint32_t a;
    asm("{ .reg .u64 t; cvta.to.shared.u64 t, %1; cvt.u32.u64 %0, t; }" : "=r"(a) : "l"(p));
    return a;
}
__device__ __forceinline__ float ex2(float x) {
    float y;
    asm("ex2.approx.ftz.f32 %0, %1;" : "=f"(y) : "f"(x));
    return y;
}
__device__ __forceinline__ void cpasync16(uint32_t dst, const void* src) {
    asm volatile("cp.async.cg.shared.global [%0], [%1], 16;" :: "r"(dst), "l"(src));
}
#define CP_COMMIT()  asm volatile("cp.async.commit_group;" ::: "memory")
#define CP_WAIT(n)   asm volatile("cp.async.wait_group " #n ";" ::: "memory")

__device__ __forceinline__ void mma16(float* c, const uint32_t* a, const uint32_t* b) {
    asm volatile(
        "mma.sync.aligned.m16n8k16.row.col.f32.f16.f16.f32 "
        "{%0,%1,%2,%3},{%4,%5,%6,%7},{%8,%9},{%0,%1,%2,%3};\n"
        : "+f"(c[0]), "+f"(c[1]), "+f"(c[2]), "+f"(c[3])
        : "r"(a[0]), "r"(a[1]), "r"(a[2]), "r"(a[3]),
          "r"(b[0]), "r"(b[1]));
}
__device__ __forceinline__ uint32_t h2u(__half2 h) {
    return *reinterpret_cast<uint32_t*>(&h);
}
#define LDSM4(r0, r1, r2, r3, addr)                                            \
    asm volatile("ldmatrix.sync.aligned.m8n8.x4.shared.b16 {%0,%1,%2,%3}, [%4];" \
                 : "=r"(r0), "=r"(r1), "=r"(r2), "=r"(r3) : "r"(addr))
#define STS64(addr, lo, hi) \
    asm volatile("st.shared.v2.b32 [%0], {%1,%2};" :: "r"(addr), "r"(lo), "r"(hi))

// ---------------- fp32 -> fp16 weight conversion (inputs converted in-GEMM) ----
#define N4W (DM * DM / 4)

__global__ void cvt_w(const float* __restrict__ Wq, const float* __restrict__ Wk,
                      const float* __restrict__ Wv, const float* __restrict__ Wo)
{
    int i = blockIdx.x * blockDim.x + threadIdx.x;
    int seg = i / N4W;
    int off = i - seg * N4W;
    const float4* s = (const float4*)(seg == 0 ? Wq : seg == 1 ? Wk : seg == 2 ? Wv : Wo);
    __half2* d = (__half2*)(g_wh + (size_t)seg * DM * DM);
    float4 v = s[off];
    d[2 * off]     = __floats2half2_rn(v.x, v.y);
    d[2 * off + 1] = __floats2half2_rn(v.z, v.w);
}

// ---------------- fp16 GEMM (mma m16n8k16 + ldmatrix, cp.async distance-2) ----------------
// C[8192,1024] = A[8192,1024(K-major)] @ W[1024,1024(K-major)]^T + bias
// CVTA=true: A read as raw fp32, converted to fp16 in-register.
#define GP    80
#define GSTG  (128 * GP * 2)     // 20480 per stage (A then B)
#define GSMEM (3 * GSTG)         // 61440

struct GArgs {
    const float*  Af[3];   // fp32 A (CVTA=true)
    const __half* A[3];    // fp16 A (CVTA=false)
    const __half* W[3];
    const float*  bias[3];
    void*         out[3];
    int mode;
};

template <bool CVTA>
__global__ void __launch_bounds__(256, 2)
gemm_h(GArgs ga)
{
    extern __shared__ char smc[];
    const uint32_t sb = smem_u32(smc);
    const int z = blockIdx.z;
    const float* __restrict__ Af   = ga.Af[z];
    const __half* __restrict__ A   = ga.A[z];
    const __half* __restrict__ W   = ga.W[z];
    const float* __restrict__ bias = ga.bias[z];
    const int mode = ga.mode;

    const int tid  = threadIdx.x;
    const int warp = tid >> 5, lane = tid & 31;
    const int g = lane >> 2, t = lane & 3;
    const int wm = warp >> 2, wn = warp & 3;
    const int bm = blockIdx.y * 128, bn = blockIdx.x * 128;
    const int lrow = lane & 7, sel = lane >> 3;

    const uint32_t offA = (uint32_t)(lrow * GP + (sel & 1) * (8 * GP) + (sel >> 1) * 16);
    const uint32_t offB = (uint32_t)(lrow * GP + (sel & 1) * 16 + (sel >> 1) * (8 * GP));

    const float*  Ab32 = Af + (size_t)bm * DM;
    const __half* Ab   = A + (size_t)bm * DM;
    const __half* Wb   = W + (size_t)bn * DM;

    float acc[4][4][4];
#pragma unroll
    for (int i = 0; i < 4; i++)
#pragma unroll
        for (int j = 0; j < 4; j++)
#pragma unroll
            for (int e = 0; e < 4; e++) acc[i][j][e] = 0.f;

#define LOAD_B(kt, stg)                                                         \
    do {                                                                        \
        uint32_t bB = sb + (stg) * GSTG + 128 * GP;                             \
        int kc = (kt) * 32;                                                     \
        _Pragma("unroll")                                                       \
        for (int i_ = 0; i_ < 2; i_++) {                                        \
            int id = tid + i_ * 256;                                            \
            int r_ = id >> 2, c4 = id & 3;                                      \
            cpasync16(bB + r_ * GP + c4 * 16, Wb + (size_t)r_ * DM + kc + c4 * 8); \
        }                                                                       \
    } while (0)

#define LOAD_A16(kt, stg)                                                       \
    do {                                                                        \
        uint32_t bA = sb + (stg) * GSTG;                                        \
        int kc = (kt) * 32;                                                     \
        _Pragma("unroll")                                                       \
        for (int i_ = 0; i_ < 2; i_++) {                                        \
            int id = tid + i_ * 256;                                            \
            int r_ = id >> 2, c4 = id & 3;                                      \
            cpasync16(bA + r_ * GP + c4 * 16, Ab + (size_t)r_ * DM + kc + c4 * 8); \
        }                                                                       \
    } while (0)

    // prologue
    if (CVTA) {
#pragma unroll
        for (int pt = 0; pt < 2; pt++) {
            uint32_t bA = sb + pt * GSTG;
#pragma unroll
            for (int i_ = 0; i_ < 4; i_++) {
                int fi = tid + i_ * 256;
                int r_ = fi >> 3, c4 = fi & 7;
                float4 f = *(const float4*)(Ab32 + (size_t)r_ * DM + pt * 32 + c4 * 4);
                STS64(bA + r_ * GP + c4 * 8,
                      h2u(__floats2half2_rn(f.x, f.y)),
                      h2u(__floats2half2_rn(f.z, f.w)));
            }
        }
        LOAD_B(0, 0); CP_COMMIT();
        LOAD_B(1, 1); CP_COMMIT();
    } else {
        LOAD_A16(0, 0); LOAD_B(0, 0); CP_COMMIT();
        LOAD_A16(1, 1); LOAD_B(1, 1); CP_COMMIT();
    }

    for (int tt = 0; tt < 32; tt++) {
        if (tt < 31) { CP_WAIT(1); } else { CP_WAIT(0); }
        __syncthreads();

        const bool pref = (tt + 2 < 32);
        float4 pre[4];
        if (pref) {
            const int stg2 = (tt + 2) % 3;
            if (CVTA) {
                int kc = (tt + 2) * 32;
#pragma unroll
                for (int i_ = 0; i_ < 4; i_++) {
                    int fi = tid + i_ * 256;
                    int r_ = fi >> 3, c4 = fi & 7;
                    pre[i_] = *(const float4*)(Ab32 + (size_t)r_ * DM + kc + c4 * 4);
                }
                LOAD_B(tt + 2, stg2);
            } else {
                LOAD_A16(tt + 2, stg2);
                LOAD_B(tt + 2, stg2);
            }
        }

        const uint32_t sAu = sb + (tt % 3) * GSTG;
        const uint32_t sBu = sAu + 128 * GP;
#pragma unroll
        for (int s = 0; s < 2; s++) {
            uint32_t af[4][4], bf[4][2];
#pragma unroll
            for (int i = 0; i < 4; i++)
                LDSM4(af[i][0], af[i][1], af[i][2], af[i][3],
                      sAu + (uint32_t)((wm * 64 + i * 16) * GP + s * 32) + offA);
#pragma unroll
            for (int j2 = 0; j2 < 2; j2++)
                LDSM4(bf[2 * j2][0], bf[2 * j2][1], bf[2 * j2 + 1][0], bf[2 * j2 + 1][1],
                      sBu + (uint32_t)((wn * 32 + j2 * 16) * GP + s * 32) + offB);
#pragma unroll
            for (int i = 0; i < 4; i++)
#pragma unroll
                for (int j = 0; j < 4; j++) mma16(acc[i][j], af[i], bf[j]);
        }

        if (CVTA && pref) {
            uint32_t bA = sb + ((tt + 2) % 3) * GSTG;
#pragma unroll
            for (int i_ = 0; i_ < 4; i_++) {
                int fi = tid + i_ * 256;
                int r_ = fi >> 3, c4 = fi & 7;
                STS64(bA + r_ * GP + c4 * 8,
                      h2u(__floats2half2_rn(pre[i_].x, pre[i_].y)),
                      h2u(__floats2half2_rn(pre[i_].z, pre[i_].w)));
            }
        }
        if (pref) CP_COMMIT();
    }
#undef LOAD_B
#undef LOAD_A16

    // epilogue
#pragma unroll
    for (int i = 0; i < 4; i++) {
#pragma unroll
        for (int j = 0; j < 4; j++) {
            int row0 = bm + wm * 64 + i * 16 + g;
            int col0 = bn + wn * 32 + j * 8 + 2 * t;
            float b0 = bias[col0], b1 = bias[col0 + 1];
            float c00 = acc[i][j][0] + b0, c01 = acc[i][j][1] + b1;
            float c10 = acc[i][j][2] + b0, c11 = acc[i][j][3] + b1;
            if (mode == 1) {
                float* out = (float*)ga.out[z];
                out[(size_t)row0 * DM + col0]           = c00;
                out[(size_t)row0 * DM + col0 + 1]       = c01;
                out[(size_t)(row0 + 8) * DM + col0]     = c10;
                out[(size_t)(row0 + 8) * DM + col0 + 1] = c11;
            } else {
                __half* out = (__half*)ga.out[z];
                int h = col0 >> 6, dh0 = col0 & 63;
                int b = row0 >> 11, s = row0 & 2047;
                if (z < 2) {
                    size_t base = (((size_t)(b * NH + h) * SS) + s) * DH + dh0;
                    *(__half2*)(out + base)          = __floats2half2_rn(c00, c01);
                    *(__half2*)(out + base + 8 * DH) = __floats2half2_rn(c10, c11);
                } else {
                    size_t base = ((size_t)(b * NH + h) * DH + dh0) * SS + s;
                    out[base]          = __float2half_rn(c00);
                    out[base + SS]     = __float2half_rn(c01);
                    out[base + 8]      = __float2half_rn(c10);
                    out[base + SS + 8] = __float2half_rn(c11);
                }
            }
        }
    }
}

// ---------------- Flash attention (fp16 mma + ldmatrix, Q in smem, occ 2) --------
// Q in smem kills the persistent 16-reg Q fragment -> fits 128 regs -> 2 CTAs/SM.
// K smem [128 kv][64 dh] pitch 144B; V^T smem [64 dh][128 kv] pitch 272B;
// Q smem [128 q][64 dh] pitch 144B. All ldmatrix phases conflict-free.
#define KPIT   144
#define VPIT   272
#define QPIT   144
#define KBYTES (128 * KPIT)          // 18432
#define VBYTES (64 * VPIT)           // 17408
#define BUFB   (KBYTES + VBYTES)     // 35840
#define QOFF   (2 * BUFB)            // 71680
#define ASMEM  (QOFF + 128 * QPIT)   // 90112  (x2 CTAs = 180224 <= 227KB)

__global__ void __launch_bounds__(256, 2)
attn_h(const __half* __restrict__ q, const __half* __restrict__ k,
       const __half* __restrict__ vt, __half* __restrict__ out)
{
    extern __shared__ char smc[];
    const uint32_t sba = smem_u32(smc);

    const int tid = threadIdx.x, warp = tid >> 5, lane = tid & 31;
    const int g = lane >> 2, t = lane & 3;
    const int bh = blockIdx.y, qt = blockIdx.x;
    const int band = warp * 16;
    const int lrow = lane & 7, sel = lane >> 3;

    const uint32_t offK = (uint32_t)(lrow * KPIT + (sel & 1) * 16 + (sel >> 1) * (8 * KPIT));
    const uint32_t offV = (uint32_t)(lrow * VPIT + (sel & 1) * 16 + (sel >> 1) * (8 * VPIT));
    const uint32_t offQ = (uint32_t)(lrow * QPIT + (sel & 1) * (8 * QPIT) + (sel >> 1) * 16);

    const __half* qb  = q  + (size_t)bh * SS * DH;
    const __half* kb  = k  + (size_t)bh * SS * DH;
    const __half* vtb = vt + (size_t)bh * DH * SS;

#define AFILL(tile, buf)                                                            \
    do {                                                                            \
        uint32_t kb_ = sba + (buf) * BUFB;                                          \
        uint32_t vb_ = kb_ + KBYTES;                                                \
        _Pragma("unroll")                                                           \
        for (int i_ = 0; i_ < 4; i_++) {                                            \
            int id = tid + i_ * 256;                                                \
            int rk = id >> 3, ck = id & 7;                                          \
            cpasync16(kb_ + rk * KPIT + ck * 16,                                    \
                      kb + (size_t)((tile) * 128 + rk) * DH + ck * 8);              \
            int rv = id >> 4, cv = id & 15;                                         \
            cpasync16(vb_ + rv * VPIT + cv * 16,                                    \
                      vtb + (size_t)rv * SS + (tile) * 128 + cv * 8);               \
        }                                                                           \
    } while (0)

    // Q tile -> smem (raw fp16 copy; softmax scale applied post-MMA on sf)
    {
        uint32_t qs = sba + QOFF;
#pragma unroll
        for (int i_ = 0; i_ < 4; i_++) {
            int id = tid + i_ * 256;
            int rq = id >> 3, cq = id & 7;
            cpasync16(qs + rq * QPIT + cq * 16,
                      qb + (size_t)(qt * 128 + rq) * DH + cq * 8);
        }
    }
    AFILL(0, 0); CP_COMMIT();

    const float SCL = 0.125f * 1.4426950408889634f;  // 1/sqrt(64) * log2(e)
    const uint32_t qrow = sba + QOFF + (uint32_t)(band * QPIT);

    float m0 = -INFINITY, m1 = -INFINITY, l0 = 0.f, l1 = 0.f;
    float oa[8][4];
#pragma unroll
    for (int j = 0; j < 8; j++)
#pragma unroll
        for (int e = 0; e < 4; e++) oa[j][e] = 0.f;

    for (int kv = 0; kv < 16; kv++) {
        CP_WAIT(0);
        __syncthreads();
        if (kv < 15) { AFILL(kv + 1, (kv + 1) & 1); CP_COMMIT(); }

        const uint32_t Ksu = sba + (kv & 1) * BUFB;
        const uint32_t Vtu = Ksu + KBYTES;

        // S = Q * K^T
        float sf[16][4];
#pragma unroll
        for (int j = 0; j < 16; j++)
#pragma unroll
            for (int e = 0; e < 4; e++) sf[j][e] = 0.f;
#pragma unroll
        for (int s = 0; s < 4; s++) {
            uint32_t qa[4];
            LDSM4(qa[0], qa[1], qa[2], qa[3], qrow + (uint32_t)(s * 32) + offQ);
#pragma unroll
            for (int j2 = 0; j2 < 8; j2++) {
                uint32_t b0[2], b1[2];
                LDSM4(b0[0], b0[1], b1[0], b1[1],
                      Ksu + (uint32_t)(j2 * 16 * KPIT + s * 32) + offK);
                mma16(sf[2 * j2],     qa, b0);
                mma16(sf[2 * j2 + 1], qa, b1);
            }
        }
        // softmax scale (log2 domain)
#pragma unroll
        for (int j = 0; j < 16; j++)
#pragma unroll
            for (int e = 0; e < 4; e++) sf[j][e] *= SCL;

        // online softmax
        float mt0 = -INFINITY, mt1 = -INFINITY;
#pragma unroll
        for (int j = 0; j < 16; j++) {
            mt0 = fmaxf(mt0, fmaxf(sf[j][0], sf[j][1]));
            mt1 = fmaxf(mt1, fmaxf(sf[j][2], sf[j][3]));
        }
        mt0 = fmaxf(mt0, __shfl_xor_sync(0xffffffffu, mt0, 1));
        mt0 = fmaxf(mt0, __shfl_xor_sync(0xffffffffu, mt0, 2));
        mt1 = fmaxf(mt1, __shfl_xor_sync(0xffffffffu, mt1, 1));
        mt1 = fmaxf(mt1, __shfl_xor_sync(0xffffffffu, mt1, 2));

        float mn0 = fmaxf(m0, mt0), mn1 = fmaxf(m1, mt1);
        float al0 = ex2(m0 - mn0), al1 = ex2(m1 - mn1);

        // P stays in registers: C-frag(S) layout == A-frag(PV) layout
        uint32_t pf[16][2];
        float rs0 = 0.f, rs1 = 0.f;
#pragma unroll
        for (int j = 0; j < 16; j++) {
            float p0 = ex2(sf[j][0] - mn0);
            float p1 = ex2(sf[j][1] - mn0);
            float p2 = ex2(sf[j][2] - mn1);
            float p3 = ex2(sf[j][3] - mn1);
            rs0 += p0 + p1;
            rs1 += p2 + p3;
            pf[j][0] = h2u(__floats2half2_rn(p0, p1));   // row g
            pf[j][1] = h2u(__floats2half2_rn(p2, p3));   // row g+8
        }
        rs0 += __shfl_xor_sync(0xffffffffu, rs0, 1);
        rs0 += __shfl_xor_sync(0xffffffffu, rs0, 2);
        rs1 += __shfl_xor_sync(0xffffffffu, rs1, 1);
        rs1 += __shfl_xor_sync(0xffffffffu, rs1, 2);

        l0 = l0 * al0 + rs0;
        l1 = l1 * al1 + rs1;
        m0 = mn0;
        m1 = mn1;
#pragma unroll
        for (int j = 0; j < 8; j++) {
            oa[j][0] *= al0; oa[j][1] *= al0;
            oa[j][2] *= al1; oa[j][3] *= al1;
        }

        // O += P * V  (P from registers, V via ldmatrix)
#pragma unroll
        for (int kk = 0; kk < 8; kk++) {
            uint32_t af[4];
            af[0] = pf[2 * kk][0];
            af[1] = pf[2 * kk][1];
            af[2] = pf[2 * kk + 1][0];
            af[3] = pf[2 * kk + 1][1];
#pragma unroll
            for (int j2 = 0; j2 < 4; j2++) {
                uint32_t b0[2], b1[2];
                LDSM4(b0[0], b0[1], b1[0], b1[1],
                      Vtu + (uint32_t)(j2 * 16 * VPIT + kk * 32) + offV);
                mma16(oa[2 * j2],     af, b0);
                mma16(oa[2 * j2 + 1], af, b1);
            }
        }
        // next iteration's top __syncthreads covers buffer reuse
    }
#undef AFILL

    float i0 = 1.f / l0, i1 = 1.f / l1;
    int b = bh >> 4, h = bh & 15;
    int tr0 = b * SS + qt * 128 + band + g;
    __half* ob0 = out + (size_t)tr0 * DM + h * DH;
    __half* ob1 = out + (size_t)(tr0 + 8) * DM + h * DH;
#pragma unroll
    for (int j = 0; j < 8; j++) {
        int c = j * 8 + 2 * t;
        *(__half2*)(ob0 + c) = __floats2half2_rn(oa[j][0] * i0, oa[j][1] * i0);
        *(__half2*)(ob1 + c) = __floats2half2_rn(oa[j][2] * i1, oa[j][3] * i1);
    }
}

// ---------------- launcher ----------------
extern "C" void kernel_launch(void* const* d_in, const int* in_sizes, int n_in,
                              void* d_out, int out_size)
{
    const float* Q  = (const float*)d_in[0];
    const float* K  = (const float*)d_in[1];
    const float* V  = (const float*)d_in[2];
    const float* Wq = (const float*)d_in[3];
    const float* bq = (const float*)d_in[4];
    const float* Wk = (const float*)d_in[5];
    const float* bk = (const float*)d_in[6];
    const float* Wv = (const float*)d_in[7];
    const float* bv = (const float*)d_in[8];
    const float* Wo = (const float*)d_in[9];
    const float* bo = (const float*)d_in[10];

    __half *qh, *kh, *vth, *ah, *wh;
    cudaGetSymbolAddress((void**)&qh,  g_qh);
    cudaGetSymbolAddress((void**)&kh,  g_kh);
    cudaGetSymbolAddress((void**)&vth, g_vth);
    cudaGetSymbolAddress((void**)&ah,  g_ah);
    cudaGetSymbolAddress((void**)&wh,  g_wh);

    cudaFuncSetAttribute(attn_h, cudaFuncAttributeMaxDynamicSharedMemorySize, ASMEM);
    cudaFuncSetAttribute(gemm_h<true>,  cudaFuncAttributeMaxDynamicSharedMemorySize, GSMEM);
    cudaFuncSetAttribute(gemm_h<false>, cudaFuncAttributeMaxDynamicSharedMemorySize, GSMEM);

    // fp32 -> fp16 weights only (inputs converted inside the QKV GEMM)
    cvt_w<<<4 * N4W / 256, 256>>>(Wq, Wk, Wv, Wo);

    // merged Q/K/V projection GEMMs: raw fp32 A, in-kernel conversion
    GArgs gp;
    gp.Af[0] = Q;    gp.Af[1] = K;    gp.Af[2] = V;
    gp.A[0] = nullptr; gp.A[1] = nullptr; gp.A[2] = nullptr;
    gp.W[0] = wh;    gp.W[1] = wh + DM * DM; gp.W[2] = wh + 2 * DM * DM;
    gp.bias[0] = bq; gp.bias[1] = bk;        gp.bias[2] = bv;
    gp.out[0] = qh;  gp.out[1] = kh;         gp.out[2] = vth;
    gp.mode = 0;
    dim3 ggrid(DM / 128, TOK / 128, 3);   // (8, 64, 3)
    gemm_h<true><<<ggrid, 256, GSMEM>>>(gp);

    dim3 agrid(SS / 128, BB * NH);        // (16, 64)
    attn_h<<<agrid, 256, ASMEM>>>(qh, kh, vth, ah);

    // output projection (fp16 A from attn, fp32 result)
    GArgs go;
    go.Af[0] = nullptr; go.Af[1] = nullptr; go.Af[2] = nullptr;
    go.A[0] = ah;  go.A[1] = ah;  go.A[2] = ah;
    go.W[0] = wh + 3 * DM * DM; go.W[1] = go.W[0]; go.W[2] = go.W[0];
    go.bias[0] = bo; go.bias[1] = bo; go.bias[2] = bo;
    go.out[0] = d_out; go.out[1] = d_out; go.out[2] = d_out;
    go.mode = 1;
    dim3 ogrid(DM / 128, TOK / 128, 1);
    gemm_h<false><<<ogrid, 256, GSMEM>>>(go);
}

// round 15
// speedup vs baseline: 2.1984x; 1.0548x over previous
#include <cuda_runtime.h>
#include <cuda_fp16.h>
#include <cstdint>

// Problem constants
#define BB    4
#define SS    2048
#define DM    1024
#define NH    16
#define DH    64
#define TOK   (BB * SS)          // 8192 tokens

// ---------------- scratch (no cudaMalloc allowed) ----------------
__device__ __half g_qh[TOK * DM];      // [B,H,S,Dh]
__device__ __half g_kh[TOK * DM];      // [B,H,S,Dh]
__device__ __half g_vth[TOK * DM];     // [B,H,Dh,S]  (V transposed)
__device__ __half g_ah[TOK * DM];      // [B,S,D]     attn output
__device__ __half g_wh[4 * DM * DM];   // fp16 weights Wq,Wk,Wv,Wo

// ---------------- helpers ----------------
__device__ __forceinline__ uint32_t smem_u32(const void* p) {
    uint32_t a;
    asm("{ .reg .u64 t; cvta.to.shared.u64 t, %1; cvt.u32.u64 %0, t; }" : "=r"(a) : "l"(p));
    return a;
}
__device__ __forceinline__ float ex2(float x) {
    float y;
    asm("ex2.approx.ftz.f32 %0, %1;" : "=f"(y) : "f"(x));
    return y;
}
__device__ __forceinline__ void cpasync16(uint32_t dst, const void* src) {
    asm volatile("cp.async.cg.shared.global [%0], [%1], 16;" :: "r"(dst), "l"(src));
}
#define CP_COMMIT()  asm volatile("cp.async.commit_group;" ::: "memory")
#define CP_WAIT(n)   asm volatile("cp.async.wait_group " #n ";" ::: "memory")

__device__ __forceinline__ void mma16(float* c, const uint32_t* a, const uint32_t* b) {
    asm volatile(
        "mma.sync.aligned.m16n8k16.row.col.f32.f16.f16.f32 "
        "{%0,%1,%2,%3},{%4,%5,%6,%7},{%8,%9},{%0,%1,%2,%3};\n"
        : "+f"(c[0]), "+f"(c[1]), "+f"(c[2]), "+f"(c[3])
        : "r"(a[0]), "r"(a[1]), "r"(a[2]), "r"(a[3]),
          "r"(b[0]), "r"(b[1]));
}
__device__ __forceinline__ uint32_t h2u(__half2 h) {
    return *reinterpret_cast<uint32_t*>(&h);
}
#define LDSM4(r0, r1, r2, r3, addr)                                            \
    asm volatile("ldmatrix.sync.aligned.m8n8.x4.shared.b16 {%0,%1,%2,%3}, [%4];" \
                 : "=r"(r0), "=r"(r1), "=r"(r2), "=r"(r3) : "r"(addr))
#define STS64(addr, lo, hi) \
    asm volatile("st.shared.v2.b32 [%0], {%1,%2};" :: "r"(addr), "r"(lo), "r"(hi))

// ---------------- fp32 -> fp16 weight conversion (inputs converted in-GEMM) ----
#define N4W (DM * DM / 4)

__global__ void cvt_w(const float* __restrict__ Wq, const float* __restrict__ Wk,
                      const float* __restrict__ Wv, const float* __restrict__ Wo)
{
    int i = blockIdx.x * blockDim.x + threadIdx.x;
    int seg = i / N4W;
    int off = i - seg * N4W;
    const float4* s = (const float4*)(seg == 0 ? Wq : seg == 1 ? Wk : seg == 2 ? Wv : Wo);
    __half2* d = (__half2*)(g_wh + (size_t)seg * DM * DM);
    float4 v = s[off];
    d[2 * off]     = __floats2half2_rn(v.x, v.y);
    d[2 * off + 1] = __floats2half2_rn(v.z, v.w);
}

// ---------------- fp16 GEMM (mma m16n8k16 + ldmatrix, K-step 64) ----------------
// C[8192,1024] = A[8192,1024(K-major)] @ W[1024,1024(K-major)]^T + bias
// K-step 64 halves barrier/wait count vs K-step 32 (16 iterations).
// Rows: 64 halves = 128B data, pitch 144B -> 16B/row bank rotation: every
// 8-row ldmatrix phase covers all 32 banks (conflict-free).
// CVTA=true: A read as raw fp32, cvt in-register (two 4xfloat4 batches/iter).
#define GP2   144
#define GAB   (128 * GP2)        // 18432 per operand
#define GSTG  (2 * GAB)          // 36864 per stage (A then B)
#define GSMEM (3 * GSTG)         // 110592  (x2 CTAs = 221184 <= 233KB)

struct GArgs {
    const float*  Af[3];   // fp32 A (CVTA=true)
    const __half* A[3];    // fp16 A (CVTA=false)
    const __half* W[3];
    const float*  bias[3];
    void*         out[3];
    int mode;
};

template <bool CVTA>
__global__ void __launch_bounds__(256, 2)
gemm_h(GArgs ga)
{
    extern __shared__ char smc[];
    const uint32_t sb = smem_u32(smc);
    const int z = blockIdx.z;
    const float* __restrict__ Af   = ga.Af[z];
    const __half* __restrict__ A   = ga.A[z];
    const __half* __restrict__ W   = ga.W[z];
    const float* __restrict__ bias = ga.bias[z];
    const int mode = ga.mode;

    const int tid  = threadIdx.x;
    const int warp = tid >> 5, lane = tid & 31;
    const int g = lane >> 2, t = lane & 3;
    const int wm = warp >> 2, wn = warp & 3;
    const int bm = blockIdx.y * 128, bn = blockIdx.x * 128;
    const int lrow = lane & 7, sel = lane >> 3;

    const uint32_t offA = (uint32_t)(lrow * GP2 + (sel & 1) * (8 * GP2) + (sel >> 1) * 16);
    const uint32_t offB = (uint32_t)(lrow * GP2 + (sel & 1) * 16 + (sel >> 1) * (8 * GP2));

    const float*  Ab32 = Af + (size_t)bm * DM;
    const __half* Ab   = A + (size_t)bm * DM;
    const __half* Wb   = W + (size_t)bn * DM;

    float acc[4][4][4];
#pragma unroll
    for (int i = 0; i < 4; i++)
#pragma unroll
        for (int j = 0; j < 4; j++)
#pragma unroll
            for (int e = 0; e < 4; e++) acc[i][j][e] = 0.f;

    // B tile: 128 rows x 64 halves (128B data/row), 4 cp.async per thread
#define LOAD_B(kt, stg)                                                         \
    do {                                                                        \
        uint32_t bB = sb + (stg) * GSTG + GAB;                                  \
        int kc = (kt) * 64;                                                     \
        _Pragma("unroll")                                                       \
        for (int i_ = 0; i_ < 4; i_++) {                                        \
            int id = tid + i_ * 256;                                            \
            int r_ = id >> 3, c_ = id & 7;                                      \
            cpasync16(bB + r_ * GP2 + c_ * 16, Wb + (size_t)r_ * DM + kc + c_ * 8); \
        }                                                                       \
    } while (0)

#define LOAD_A16(kt, stg)                                                       \
    do {                                                                        \
        uint32_t bA = sb + (stg) * GSTG;                                        \
        int kc = (kt) * 64;                                                     \
        _Pragma("unroll")                                                       \
        for (int i_ = 0; i_ < 4; i_++) {                                        \
            int id = tid + i_ * 256;                                            \
            int r_ = id >> 3, c_ = id & 7;                                      \
            cpasync16(bA + r_ * GP2 + c_ * 16, Ab + (size_t)r_ * DM + kc + c_ * 8); \
        }                                                                       \
    } while (0)

    // fp32 A batch LDG / STS (batch bt in {0,1}: 4 float4 per thread)
#define LDG_A32(kt, bt, pre)                                                    \
    do {                                                                        \
        int kc = (kt) * 64;                                                     \
        _Pragma("unroll")                                                       \
        for (int i_ = 0; i_ < 4; i_++) {                                        \
            int id = tid + ((bt) * 4 + i_) * 256;                               \
            int r_ = id >> 4, c4 = id & 15;                                     \
            (pre)[i_] = *(const float4*)(Ab32 + (size_t)r_ * DM + kc + c4 * 4); \
        }                                                                       \
    } while (0)

#define STS_A32(stg, bt, pre)                                                   \
    do {                                                                        \
        uint32_t bA = sb + (stg) * GSTG;                                        \
        _Pragma("unroll")                                                       \
        for (int i_ = 0; i_ < 4; i_++) {                                        \
            int id = tid + ((bt) * 4 + i_) * 256;                               \
            int r_ = id >> 4, c4 = id & 15;                                     \
            STS64(bA + r_ * GP2 + c4 * 8,                                       \
                  h2u(__floats2half2_rn((pre)[i_].x, (pre)[i_].y)),             \
                  h2u(__floats2half2_rn((pre)[i_].z, (pre)[i_].w)));            \
        }                                                                       \
    } while (0)

    // prologue: tiles 0,1
    if (CVTA) {
        float4 p0[4];
#pragma unroll
        for (int pt = 0; pt < 2; pt++) {
            LDG_A32(pt, 0, p0); STS_A32(pt, 0, p0);
            LDG_A32(pt, 1, p0); STS_A32(pt, 1, p0);
        }
        LOAD_B(0, 0); CP_COMMIT();
        LOAD_B(1, 1); CP_COMMIT();
    } else {
        LOAD_A16(0, 0); LOAD_B(0, 0); CP_COMMIT();
        LOAD_A16(1, 1); LOAD_B(1, 1); CP_COMMIT();
    }

    for (int tt = 0; tt < 16; tt++) {
        if (tt < 15) { CP_WAIT(1); } else { CP_WAIT(0); }
        __syncthreads();

        const bool pref = (tt + 2 < 16);
        const int stg2 = (tt + 2) % 3;
        float4 pre[4];
        if (pref) {
            if (CVTA) {
                LDG_A32(tt + 2, 0, pre);   // batch0 in flight over s=0,1
                LOAD_B(tt + 2, stg2);
            } else {
                LOAD_A16(tt + 2, stg2);
                LOAD_B(tt + 2, stg2);
            }
        }

        const uint32_t sAu = sb + (tt % 3) * GSTG;
        const uint32_t sBu = sAu + GAB;

#define COMPUTE_S(s)                                                            \
        do {                                                                    \
            uint32_t af[4][4], bf[4][2];                                        \
            _Pragma("unroll")                                                   \
            for (int i = 0; i < 4; i++)                                         \
                LDSM4(af[i][0], af[i][1], af[i][2], af[i][3],                   \
                      sAu + (uint32_t)((wm * 64 + i * 16) * GP2 + (s) * 32) + offA); \
            _Pragma("unroll")                                                   \
            for (int j2 = 0; j2 < 2; j2++)                                      \
                LDSM4(bf[2 * j2][0], bf[2 * j2][1], bf[2 * j2 + 1][0], bf[2 * j2 + 1][1], \
                      sBu + (uint32_t)((wn * 32 + j2 * 16) * GP2 + (s) * 32) + offB); \
            _Pragma("unroll")                                                   \
            for (int i = 0; i < 4; i++)                                         \
                _Pragma("unroll")                                               \
                for (int j = 0; j < 4; j++) mma16(acc[i][j], af[i], bf[j]);     \
        } while (0)

        COMPUTE_S(0);
        COMPUTE_S(1);
        if (CVTA && pref) {
            STS_A32(stg2, 0, pre);
            LDG_A32(tt + 2, 1, pre);       // batch1 in flight over s=2,3
        }
        COMPUTE_S(2);
        COMPUTE_S(3);
        if (CVTA && pref) STS_A32(stg2, 1, pre);
        if (pref) CP_COMMIT();
#undef COMPUTE_S
    }
#undef LOAD_B
#undef LOAD_A16
#undef LDG_A32
#undef STS_A32

    // epilogue
#pragma unroll
    for (int i = 0; i < 4; i++) {
#pragma unroll
        for (int j = 0; j < 4; j++) {
            int row0 = bm + wm * 64 + i * 16 + g;
            int col0 = bn + wn * 32 + j * 8 + 2 * t;
            float b0 = bias[col0], b1 = bias[col0 + 1];
            float c00 = acc[i][j][0] + b0, c01 = acc[i][j][1] + b1;
            float c10 = acc[i][j][2] + b0, c11 = acc[i][j][3] + b1;
            if (mode == 1) {
                float* out = (float*)ga.out[z];
                out[(size_t)row0 * DM + col0]           = c00;
                out[(size_t)row0 * DM + col0 + 1]       = c01;
                out[(size_t)(row0 + 8) * DM + col0]     = c10;
                out[(size_t)(row0 + 8) * DM + col0 + 1] = c11;
            } else {
                __half* out = (__half*)ga.out[z];
                int h = col0 >> 6, dh0 = col0 & 63;
                int b = row0 >> 11, s = row0 & 2047;
                if (z < 2) {
                    size_t base = (((size_t)(b * NH + h) * SS) + s) * DH + dh0;
                    *(__half2*)(out + base)          = __floats2half2_rn(c00, c01);
                    *(__half2*)(out + base + 8 * DH) = __floats2half2_rn(c10, c11);
                } else {
                    size_t base = ((size_t)(b * NH + h) * DH + dh0) * SS + s;
                    out[base]          = __float2half_rn(c00);
                    out[base + SS]     = __float2half_rn(c01);
                    out[base + 8]      = __float2half_rn(c10);
                    out[base + SS + 8] = __float2half_rn(c11);
                }
            }
        }
    }
}

// ---------------- Flash attention (fp16 mma + ldmatrix, Q in smem, occ 2) --------
#define KPIT   144
#define VPIT   272
#define QPIT   144
#define KBYTES (128 * KPIT)          // 18432
#define VBYTES (64 * VPIT)           // 17408
#define BUFB   (KBYTES + VBYTES)     // 35840
#define QOFF   (2 * BUFB)            // 71680
#define ASMEM  (QOFF + 128 * QPIT)   // 90112  (x2 CTAs = 180224 <= 227KB)

__global__ void __launch_bounds__(256, 2)
attn_h(const __half* __restrict__ q, const __half* __restrict__ k,
       const __half* __restrict__ vt, __half* __restrict__ out)
{
    extern __shared__ char smc[];
    const uint32_t sba = smem_u32(smc);

    const int tid = threadIdx.x, warp = tid >> 5, lane = tid & 31;
    const int g = lane >> 2, t = lane & 3;
    const int bh = blockIdx.y, qt = blockIdx.x;
    const int band = warp * 16;
    const int lrow = lane & 7, sel = lane >> 3;

    const uint32_t offK = (uint32_t)(lrow * KPIT + (sel & 1) * 16 + (sel >> 1) * (8 * KPIT));
    const uint32_t offV = (uint32_t)(lrow * VPIT + (sel & 1) * 16 + (sel >> 1) * (8 * VPIT));
    const uint32_t offQ = (uint32_t)(lrow * QPIT + (sel & 1) * (8 * QPIT) + (sel >> 1) * 16);

    const __half* qb  = q  + (size_t)bh * SS * DH;
    const __half* kb  = k  + (size_t)bh * SS * DH;
    const __half* vtb = vt + (size_t)bh * DH * SS;

#define AFILL(tile, buf)                                                            \
    do {                                                                            \
        uint32_t kb_ = sba + (buf) * BUFB;                                          \
        uint32_t vb_ = kb_ + KBYTES;                                                \
        _Pragma("unroll")                                                           \
        for (int i_ = 0; i_ < 4; i_++) {                                            \
            int id = tid + i_ * 256;                                                \
            int rk = id >> 3, ck = id & 7;                                          \
            cpasync16(kb_ + rk * KPIT + ck * 16,                                    \
                      kb + (size_t)((tile) * 128 + rk) * DH + ck * 8);              \
            int rv = id >> 4, cv = id & 15;                                         \
            cpasync16(vb_ + rv * VPIT + cv * 16,                                    \
                      vtb + (size_t)rv * SS + (tile) * 128 + cv * 8);               \
        }                                                                           \
    } while (0)

    // Q tile -> smem (raw fp16 copy; softmax scale applied post-MMA on sf)
    {
        uint32_t qs = sba + QOFF;
#pragma unroll
        for (int i_ = 0; i_ < 4; i_++) {
            int id = tid + i_ * 256;
            int rq = id >> 3, cq = id & 7;
            cpasync16(qs + rq * QPIT + cq * 16,
                      qb + (size_t)(qt * 128 + rq) * DH + cq * 8);
        }
    }
    AFILL(0, 0); CP_COMMIT();

    const float SCL = 0.125f * 1.4426950408889634f;  // 1/sqrt(64) * log2(e)
    const uint32_t qrow = sba + QOFF + (uint32_t)(band * QPIT);

    float m0 = -INFINITY, m1 = -INFINITY, l0 = 0.f, l1 = 0.f;
    float oa[8][4];
#pragma unroll
    for (int j = 0; j < 8; j++)
#pragma unroll
        for (int e = 0; e < 4; e++) oa[j][e] = 0.f;

    for (int kv = 0; kv < 16; kv++) {
        CP_WAIT(0);
        __syncthreads();
        if (kv < 15) { AFILL(kv + 1, (kv + 1) & 1); CP_COMMIT(); }

        const uint32_t Ksu = sba + (kv & 1) * BUFB;
        const uint32_t Vtu = Ksu + KBYTES;

        // S = Q * K^T
        float sf[16][4];
#pragma unroll
        for (int j = 0; j < 16; j++)
#pragma unroll
            for (int e = 0; e < 4; e++) sf[j][e] = 0.f;
#pragma unroll
        for (int s = 0; s < 4; s++) {
            uint32_t qa[4];
            LDSM4(qa[0], qa[1], qa[2], qa[3], qrow + (uint32_t)(s * 32) + offQ);
#pragma unroll
            for (int j2 = 0; j2 < 8; j2++) {
                uint32_t b0[2], b1[2];
                LDSM4(b0[0], b0[1], b1[0], b1[1],
                      Ksu + (uint32_t)(j2 * 16 * KPIT + s * 32) + offK);
                mma16(sf[2 * j2],     qa, b0);
                mma16(sf[2 * j2 + 1], qa, b1);
            }
        }
        // softmax scale (log2 domain)
#pragma unroll
        for (int j = 0; j < 16; j++)
#pragma unroll
            for (int e = 0; e < 4; e++) sf[j][e] *= SCL;

        // online softmax
        float mt0 = -INFINITY, mt1 = -INFINITY;
#pragma unroll
        for (int j = 0; j < 16; j++) {
            mt0 = fmaxf(mt0, fmaxf(sf[j][0], sf[j][1]));
            mt1 = fmaxf(mt1, fmaxf(sf[j][2], sf[j][3]));
        }
        mt0 = fmaxf(mt0, __shfl_xor_sync(0xffffffffu, mt0, 1));
        mt0 = fmaxf(mt0, __shfl_xor_sync(0xffffffffu, mt0, 2));
        mt1 = fmaxf(mt1, __shfl_xor_sync(0xffffffffu, mt1, 1));
        mt1 = fmaxf(mt1, __shfl_xor_sync(0xffffffffu, mt1, 2));

        float mn0 = fmaxf(m0, mt0), mn1 = fmaxf(m1, mt1);
        float al0 = ex2(m0 - mn0), al1 = ex2(m1 - mn1);

        // P stays in registers: C-frag(S) layout == A-frag(PV) layout
        uint32_t pf[16][2];
        float rs0 = 0.f, rs1 = 0.f;
#pragma unroll
        for (int j = 0; j < 16; j++) {
            float p0 = ex2(sf[j][0] - mn0);
            float p1 = ex2(sf[j][1] - mn0);
            float p2 = ex2(sf[j][2] - mn1);
            float p3 = ex2(sf[j][3] - mn1);
            rs0 += p0 + p1;
            rs1 += p2 + p3;
            pf[j][0] = h2u(__floats2half2_rn(p0, p1));   // row g
            pf[j][1] = h2u(__floats2half2_rn(p2, p3));   // row g+8
        }
        rs0 += __shfl_xor_sync(0xffffffffu, rs0, 1);
        rs0 += __shfl_xor_sync(0xffffffffu, rs0, 2);
        rs1 += __shfl_xor_sync(0xffffffffu, rs1, 1);
        rs1 += __shfl_xor_sync(0xffffffffu, rs1, 2);

        l0 = l0 * al0 + rs0;
        l1 = l1 * al1 + rs1;
        m0 = mn0;
        m1 = mn1;
#pragma unroll
        for (int j = 0; j < 8; j++) {
            oa[j][0] *= al0; oa[j][1] *= al0;
            oa[j][2] *= al1; oa[j][3] *= al1;
        }

        // O += P * V  (P from registers, V via ldmatrix)
#pragma unroll
        for (int kk = 0; kk < 8; kk++) {
            uint32_t af[4];
            af[0] = pf[2 * kk][0];
            af[1] = pf[2 * kk][1];
            af[2] = pf[2 * kk + 1][0];
            af[3] = pf[2 * kk + 1][1];
#pragma unroll
            for (int j2 = 0; j2 < 4; j2++) {
                uint32_t b0[2], b1[2];
                LDSM4(b0[0], b0[1], b1[0], b1[1],
                      Vtu + (uint32_t)(j2 * 16 * VPIT + kk * 32) + offV);
                mma16(oa[2 * j2],     af, b0);
                mma16(oa[2 * j2 + 1], af, b1);
            }
        }
        // next iteration's top __syncthreads covers buffer reuse
    }
#undef AFILL

    float i0 = 1.f / l0, i1 = 1.f / l1;
    int b = bh >> 4, h = bh & 15;
    int tr0 = b * SS + qt * 128 + band + g;
    __half* ob0 = out + (size_t)tr0 * DM + h * DH;
    __half* ob1 = out + (size_t)(tr0 + 8) * DM + h * DH;
#pragma unroll
    for (int j = 0; j < 8; j++) {
        int c = j * 8 + 2 * t;
        *(__half2*)(ob0 + c) = __floats2half2_rn(oa[j][0] * i0, oa[j][1] * i0);
        *(__half2*)(ob1 + c) = __floats2half2_rn(oa[j][2] * i1, oa[j][3] * i1);
    }
}

// ---------------- launcher ----------------
extern "C" void kernel_launch(void* const* d_in, const int* in_sizes, int n_in,
                              void* d_out, int out_size)
{
    const float* Q  = (const float*)d_in[0];
    const float* K  = (const float*)d_in[1];
    const float* V  = (const float*)d_in[2];
    const float* Wq = (const float*)d_in[3];
    const float* bq = (const float*)d_in[4];
    const float* Wk = (const float*)d_in[5];
    const float* bk = (const float*)d_in[6];
    const float* Wv = (const float*)d_in[7];
    const float* bv = (const float*)d_in[8];
    const float* Wo = (const float*)d_in[9];
    const float* bo = (const float*)d_in[10];

    __half *qh, *kh, *vth, *ah, *wh;
    cudaGetSymbolAddress((void**)&qh,  g_qh);
    cudaGetSymbolAddress((void**)&kh,  g_kh);
    cudaGetSymbolAddress((void**)&vth, g_vth);
    cudaGetSymbolAddress((void**)&ah,  g_ah);
    cudaGetSymbolAddress((void**)&wh,  g_wh);

    cudaFuncSetAttribute(attn_h, cudaFuncAttributeMaxDynamicSharedMemorySize, ASMEM);
    cudaFuncSetAttribute(gemm_h<true>,  cudaFuncAttributeMaxDynamicSharedMemorySize, GSMEM);
    cudaFuncSetAttribute(gemm_h<false>, cudaFuncAttributeMaxDynamicSharedMemorySize, GSMEM);

    // fp32 -> fp16 weights only (inputs converted inside the QKV GEMM)
    cvt_w<<<4 * N4W / 256, 256>>>(Wq, Wk, Wv, Wo);

    // merged Q/K/V projection GEMMs: raw fp32 A, in-kernel conversion
    GArgs gp;
    gp.Af[0] = Q;    gp.Af[1] = K;    gp.Af[2] = V;
    gp.A[0] = nullptr; gp.A[1] = nullptr; gp.A[2] = nullptr;
    gp.W[0] = wh;    gp.W[1] = wh + DM * DM; gp.W[2] = wh + 2 * DM * DM;
    gp.bias[0] = bq; gp.bias[1] = bk;        gp.bias[2] = bv;
    gp.out[0] = qh;  gp.out[1] = kh;         gp.out[2] = vth;
    gp.mode = 0;
    dim3 ggrid(DM / 128, TOK / 128, 3);   // (8, 64, 3)
    gemm_h<true><<<ggrid, 256, GSMEM>>>(gp);

    dim3 agrid(SS / 128, BB * NH);        // (16, 64)
    attn_h<<<agrid, 256, ASMEM>>>(qh, kh, vth, ah);

    // output projection (fp16 A from attn, fp32 result)
    GArgs go;
    go.Af[0] = nullptr; go.Af[1] = nullptr; go.Af[2] = nullptr;
    go.A[0] = ah;  go.A[1] = ah;  go.A[2] = ah;
    go.W[0] = wh + 3 * DM * DM; go.W[1] = go.W[0]; go.W[2] = go.W[0];
    go.bias[0] = bo; go.bias[1] = bo; go.bias[2] = bo;
    go.out[0] = d_out; go.out[1] = d_out; go.out[2] = d_out;
    go.mode = 1;
    dim3 ogrid(DM / 128, TOK / 128, 1);
    gemm_h<false><<<ogrid, 256, GSMEM>>>(go);
}